// round 10
// baseline (speedup 1.0000x reference)
#include <cuda_runtime.h>
#include <cuda_fp16.h>
#include <math.h>
#include <stdint.h>

// ---------------- problem constants ----------------
constexpr int B_   = 32;
constexpr int C_   = 256;
constexpr int N_   = 1024;
constexpr int C3_  = 768;
constexpr int MTOT = B_ * N_;   // 32768

// ---------------- scratch (half intermediates) ----------------
__device__ float  g_mean[C_];
__device__ float  g_rstd[C_];
__device__ __half g_t  [(size_t)MTOT * C_];    // [B,N,C]
__device__ __half g_kqv[(size_t)MTOT * C3_];   // [B,N,3C] (Q,K used)
__device__ __half g_s  [(size_t)B_ * N_ * N_]; // [B,N,N] scaled scores
__device__ __half g_vt [(size_t)B_ * C_ * N_]; // [B,C,N] V^T
__device__ __half g_o  [(size_t)MTOT * C_];    // [B,N,C]
__device__ __half g_wk [(size_t)C3_ * C_];     // W_kqv fp16
__device__ __half g_wp [(size_t)C_ * C_];      // W_proj fp16
__device__ float  g_pm [(size_t)B_ * 4 * N_];  // per-tile row max (4 tiles of 256)
__device__ float  g_pl [(size_t)B_ * 4 * N_];  // per-tile row expsum
__device__ float2 g_ml [(size_t)B_ * N_];      // (rowmax, 1/rowsum)

// ---------------- PTX helpers ----------------
__device__ __forceinline__ uint32_t smem_u32(const void* p) {
    return (uint32_t)__cvta_generic_to_shared(p);
}
__device__ __forceinline__ void mma_fp16(float c[4], const uint32_t a[4], const uint32_t b[2]) {
    asm volatile(
        "mma.sync.aligned.m16n8k16.row.col.f32.f16.f16.f32 "
        "{%0,%1,%2,%3}, {%4,%5,%6,%7}, {%8,%9}, {%0,%1,%2,%3};"
        : "+f"(c[0]), "+f"(c[1]), "+f"(c[2]), "+f"(c[3])
        : "r"(a[0]), "r"(a[1]), "r"(a[2]), "r"(a[3]), "r"(b[0]), "r"(b[1]));
}
#define LDSM_X4(r0, r1, r2, r3, addr) \
    asm volatile("ldmatrix.sync.aligned.m8n8.x4.shared.b16 {%0,%1,%2,%3}, [%4];" \
        : "=r"(r0), "=r"(r1), "=r"(r2), "=r"(r3) : "r"(addr))
#define CP_ASYNC16(dst, src) \
    asm volatile("cp.async.cg.shared.global [%0], [%1], 16;" :: "r"(dst), "l"(src))
#define CP_ASYNC_COMMIT() asm volatile("cp.async.commit_group;" ::: "memory")
#define CP_ASYNC_WAIT(n)  asm volatile("cp.async.wait_group %0;" :: "n"(n) : "memory")

// ---------------- fused fp16 GEMM family (fp32 accumulate) ----------------
// C = alpha * A * B^T; A [M,K] halves (lda), B [N,K] halves (ldb).
// CTA tile 128(M) x 256(N), K-chunk 64 halves. 512 thr = 16 warps (2M x 8N),
// warp tile 64x32, 4x4 m16n8k16 MMAs per k16-step. 3-stage cp.async pipe.
constexpr int MODE_KQV  = 0;
constexpr int MODE_QK   = 1;
constexpr int MODE_AV   = 2;
constexpr int MODE_PROJ = 3;

constexpr int NT           = 512;
constexpr int ROW_B        = 144;                // padded row stride (bytes)
constexpr int A_TILE_BYTES = 128 * ROW_B;        // 18432
constexpr int B_TILE_BYTES = 256 * ROW_B;        // 36864
constexpr int STAGE_BYTES  = A_TILE_BYTES + B_TILE_BYTES;  // 55296
constexpr int SMEM_DYN     = 3 * STAGE_BYTES;    // 165888 (1 CTA/SM)

template <int MODE>
__global__ __launch_bounds__(NT, 1)
void tc_gemm(const __half* __restrict__ A, const __half* __restrict__ Bm,
             const float* __restrict__ bias, void* __restrict__ Cm,
             const void* __restrict__ P0,
             int K, int lda, int ldb, int ldc,
             long sA, long sB, long sC, float alpha) {
    extern __shared__ float sm[];

    const int tid  = threadIdx.x;
    const int lane = tid & 31;
    const int warp = tid >> 5;          // 0..15
    const int wm   = warp & 1;          // M half
    const int wn   = warp >> 1;         // 0..7 (N, 32 cols each)
    const int g    = lane >> 2;
    const int q    = lane & 3;

    const int m0 = blockIdx.y * 128;
    const int n0 = blockIdx.x * 256;
    const __half* Ab = A  + (size_t)blockIdx.z * sA;
    const __half* Bb = Bm + (size_t)blockIdx.z * sB;

    const uint32_t smb = smem_u32(sm);

    const uint32_t a_lo =
        (uint32_t)((wm * 64 + (lane & 15)) * ROW_B + (lane >> 4) * 16);
    const uint32_t b_lo =
        (uint32_t)((wn * 32 + ((lane >> 4) & 1) * 8 + (lane & 7)) * ROW_B +
                   ((lane >> 3) & 1) * 16);

    auto load_stage = [&](int slot, int kc) {
        const uint32_t abase = smb + slot * STAGE_BYTES;
        const uint32_t bbase = abase + A_TILE_BYTES;
        if (MODE != MODE_AV) {
            const __half* Asrc = Ab + (size_t)m0 * lda + kc * 64;
            #pragma unroll
            for (int j = 0; j < 2; j++) {            // 128 rows x 8 groups / 512
                int i = tid + j * NT;
                int row = i >> 3, kg = i & 7;
                CP_ASYNC16(abase + (uint32_t)(row * ROW_B + kg * 16),
                           Asrc + (size_t)row * lda + kg * 8);
            }
        }
        const __half* Bsrc = Bb + (size_t)n0 * ldb + kc * 64;
        #pragma unroll
        for (int j = 0; j < 4; j++) {                // 256 rows x 8 groups / 512
            int i = tid + j * NT;
            int row = i >> 3, kg = i & 7;
            CP_ASYNC16(bbase + (uint32_t)(row * ROW_B + kg * 16),
                       Bsrc + (size_t)row * ldb + kg * 8);
        }
        CP_ASYNC_COMMIT();
    };

    // AV: A (scores) via LDG -> exp -> half -> STS
    uint4  pend[2];
    float2 mlv[2];
    if (MODE == MODE_AV) {
        #pragma unroll
        for (int j = 0; j < 2; j++) {
            int row = (tid + j * NT) >> 3;
            mlv[j] = g_ml[(size_t)blockIdx.z * N_ + m0 + row];
        }
    }
    auto ldgA = [&](int kc) {
        #pragma unroll
        for (int j = 0; j < 2; j++) {
            int i = tid + j * NT;
            int row = i >> 3, kg = i & 7;
            pend[j] = *reinterpret_cast<const uint4*>(
                Ab + (size_t)(m0 + row) * lda + kc * 64 + kg * 8);
        }
    };
    auto stsA = [&](int slot) {
        #pragma unroll
        for (int j = 0; j < 2; j++) {
            int i = tid + j * NT;
            int row = i >> 3, kg = i & 7;
            const float m = mlv[j].x, il = mlv[j].y;
            const __half2* h = reinterpret_cast<const __half2*>(&pend[j]);
            uint4 outv;
            __half2* ho = reinterpret_cast<__half2*>(&outv);
            #pragma unroll
            for (int p = 0; p < 4; p++) {
                float2 f = __half22float2(h[p]);
                f.x = __expf(f.x - m) * il;
                f.y = __expf(f.y - m) * il;
                ho[p] = __float22half2_rn(f);
            }
            *reinterpret_cast<uint4*>(
                reinterpret_cast<char*>(sm) + slot * STAGE_BYTES +
                row * ROW_B + kg * 16) = outv;
        }
    };

    float acc[4][4][4] = {};
    const int nk = K >> 6;               // K-chunks of 64 (>=4 all call sites)

    if (MODE == MODE_AV) { ldgA(0); stsA(0); }
    load_stage(0, 0);
    load_stage(1, 1);

    for (int ks = 0; ks < nk; ks++) {
        CP_ASYNC_WAIT(1);
        __syncthreads();
        if (MODE == MODE_AV) { if (ks + 1 < nk) ldgA(ks + 1); }
        if (ks + 2 < nk) load_stage((ks + 2) % 3, ks + 2);
        else             CP_ASYNC_COMMIT();

        const uint32_t abase = smb + (ks % 3) * STAGE_BYTES;
        const uint32_t bbase = abase + A_TILE_BYTES;

        #pragma unroll
        for (int kk = 0; kk < 4; kk++) {
            uint32_t af[4][4], bf[4][2];
            #pragma unroll
            for (int tm = 0; tm < 4; tm++) {
                LDSM_X4(af[tm][0], af[tm][1], af[tm][2], af[tm][3],
                        abase + a_lo + (uint32_t)(tm * 16 * ROW_B + kk * 32));
            }
            #pragma unroll
            for (int tnp = 0; tnp < 2; tnp++) {
                LDSM_X4(bf[2 * tnp][0], bf[2 * tnp][1], bf[2 * tnp + 1][0], bf[2 * tnp + 1][1],
                        bbase + b_lo + (uint32_t)(tnp * 16 * ROW_B + kk * 32));
            }
            #pragma unroll
            for (int tm = 0; tm < 4; tm++)
                #pragma unroll
                for (int tn = 0; tn < 4; tn++)
                    mma_fp16(acc[tm][tn], af[tm], bf[tn]);
        }
        if (MODE == MODE_AV) { if (ks + 1 < nk) stsA((ks + 1) % 3); }
    }

    // ---------------- epilogues ----------------
    const bool transout = (MODE == MODE_PROJ) || (MODE == MODE_KQV && n0 >= 512);
    if (transout) {
        __syncthreads();
        float* ws = sm + warp * (64 * 33);   // 16 warps x 8448 B = 135168 <= SMEM
        #pragma unroll
        for (int tm = 0; tm < 4; tm++) {
            #pragma unroll
            for (int tn = 0; tn < 4; tn++) {
                const int r  = tm * 16 + g;
                const int cb = tn * 8 + 2 * q;
                float b0 = __ldg(&bias[n0 + wn * 32 + cb]);
                float b1 = __ldg(&bias[n0 + wn * 32 + cb + 1]);
                ws[r * 33 + cb]           = acc[tm][tn][0] * alpha + b0;
                ws[r * 33 + cb + 1]       = acc[tm][tn][1] * alpha + b1;
                ws[(r + 8) * 33 + cb]     = acc[tm][tn][2] * alpha + b0;
                ws[(r + 8) * 33 + cb + 1] = acc[tm][tn][3] * alpha + b1;
            }
        }
        __syncwarp();
        const int b     = m0 >> 10;
        const int nbase = (m0 & 1023) + wm * 64;
        #pragma unroll 4
        for (int c = 0; c < 32; c++) {
            float v0 = ws[lane * 33 + c];
            float v1 = ws[(lane + 32) * 33 + c];
            if (MODE == MODE_PROJ) {
                const int cg = n0 + wn * 32 + c;
                const size_t o0 = (((size_t)(b * C_ + cg)) << 10) + nbase;
                const float* xr = (const float*)P0;
                ((float*)Cm)[o0 + lane]      = v0 + xr[o0 + lane];
                ((float*)Cm)[o0 + 32 + lane] = v1 + xr[o0 + 32 + lane];
            } else {
                const int cg = (n0 - 512) + wn * 32 + c;
                const size_t o0 = (((size_t)(b * C_ + cg)) << 10) + nbase;
                g_vt[o0 + lane]      = __float2half_rn(v0);
                g_vt[o0 + 32 + lane] = __float2half_rn(v1);
            }
        }
        return;
    }

    // standard store (half output)
    {
        __half* Cb = (__half*)Cm + (size_t)blockIdx.z * sC;
        #pragma unroll
        for (int tm = 0; tm < 4; tm++) {
            const int row = m0 + wm * 64 + tm * 16 + g;
            #pragma unroll
            for (int tn = 0; tn < 4; tn++) {
                const int col = n0 + wn * 32 + tn * 8 + 2 * q;
                float b0 = 0.f, b1 = 0.f;
                if (MODE == MODE_KQV) { b0 = __ldg(&bias[col]); b1 = __ldg(&bias[col + 1]); }
                __half2 v0 = __floats2half2_rn(acc[tm][tn][0] * alpha + b0,
                                               acc[tm][tn][1] * alpha + b1);
                __half2 v1 = __floats2half2_rn(acc[tm][tn][2] * alpha + b0,
                                               acc[tm][tn][3] * alpha + b1);
                *reinterpret_cast<__half2*>(&Cb[(size_t)row * ldc + col])       = v0;
                *reinterpret_cast<__half2*>(&Cb[(size_t)(row + 8) * ldc + col]) = v1;
            }
        }
    }

    if (MODE == MODE_QK) {
        // softmax partials for this 128x256 tile
        float* redm = sm;           // [8][128]
        float* redl = sm + 1024;    // [8][128]
        __syncthreads();

        #pragma unroll
        for (int tm = 0; tm < 4; tm++) {
            float mx0 = -1e30f, mx1 = -1e30f;
            #pragma unroll
            for (int tn = 0; tn < 4; tn++) {
                mx0 = fmaxf(mx0, fmaxf(acc[tm][tn][0], acc[tm][tn][1]));
                mx1 = fmaxf(mx1, fmaxf(acc[tm][tn][2], acc[tm][tn][3]));
            }
            mx0 = fmaxf(mx0, __shfl_xor_sync(~0u, mx0, 1));
            mx0 = fmaxf(mx0, __shfl_xor_sync(~0u, mx0, 2));
            mx1 = fmaxf(mx1, __shfl_xor_sync(~0u, mx1, 1));
            mx1 = fmaxf(mx1, __shfl_xor_sync(~0u, mx1, 2));
            if (q == 0) {
                redm[wn * 128 + wm * 64 + tm * 16 + g]     = mx0 * alpha;
                redm[wn * 128 + wm * 64 + tm * 16 + g + 8] = mx1 * alpha;
            }
        }
        __syncthreads();
        #pragma unroll
        for (int tm = 0; tm < 4; tm++) {
            const int r0 = wm * 64 + tm * 16 + g, r1 = r0 + 8;
            float t0 = -1e30f, t1 = -1e30f;
            #pragma unroll
            for (int w = 0; w < 8; w++) {
                t0 = fmaxf(t0, redm[w * 128 + r0]);
                t1 = fmaxf(t1, redm[w * 128 + r1]);
            }
            float s0 = 0.f, s1 = 0.f;
            #pragma unroll
            for (int tn = 0; tn < 4; tn++) {
                s0 += __expf(acc[tm][tn][0] * alpha - t0);
                s0 += __expf(acc[tm][tn][1] * alpha - t0);
                s1 += __expf(acc[tm][tn][2] * alpha - t1);
                s1 += __expf(acc[tm][tn][3] * alpha - t1);
            }
            s0 += __shfl_xor_sync(~0u, s0, 1);
            s0 += __shfl_xor_sync(~0u, s0, 2);
            s1 += __shfl_xor_sync(~0u, s1, 1);
            s1 += __shfl_xor_sync(~0u, s1, 2);
            if (q == 0) { redl[wn * 128 + r0] = s0; redl[wn * 128 + r1] = s1; }
        }
        __syncthreads();
        if (tid < 128) {
            float m = -1e30f;
            #pragma unroll
            for (int w = 0; w < 8; w++) m = fmaxf(m, redm[w * 128 + tid]);
            float l = 0.f;
            #pragma unroll
            for (int w = 0; w < 8; w++) l += redl[w * 128 + tid];
            const size_t pi = ((size_t)blockIdx.z * 4 + blockIdx.x) * N_ + m0 + tid;
            g_pm[pi] = m;
            g_pl[pi] = l;
        }
    }
}

// ---------------- combine partials -> (rowmax, 1/rowsum) -----------------
__global__ void reduce_ml_kernel() {
    const int idx = blockIdx.x * 256 + threadIdx.x;
    const int b = idx >> 10, row = idx & 1023;
    float m = -1e30f;
    #pragma unroll
    for (int t = 0; t < 4; t++)
        m = fmaxf(m, g_pm[((size_t)b * 4 + t) * N_ + row]);
    float l = 0.f;
    #pragma unroll
    for (int t = 0; t < 4; t++) {
        const size_t i = ((size_t)b * 4 + t) * N_ + row;
        l += g_pl[i] * __expf(g_pm[i] - m);
    }
    g_ml[(size_t)b * N_ + row] = make_float2(m, 1.0f / l);
}

// ---------------- convert weights to fp16 ----------------
__global__ void cvt_w_kernel(const float* __restrict__ wk, const float* __restrict__ wp) {
    const int i = blockIdx.x * 256 + threadIdx.x;
    if (i < C3_ * C_) g_wk[i] = __float2half_rn(wk[i]);
    if (i < C_ * C_)  g_wp[i] = __float2half_rn(wp[i]);
}

// ---------------- BN stats (float4) ----------------
__global__ void bn_stats_kernel(const float* __restrict__ x) {
    const int c = blockIdx.x, tid = threadIdx.x;
    float s = 0.f, ss = 0.f;
    const int NP4 = N_ / 4;   // 256
    for (int i = tid; i < B_ * NP4; i += 256) {
        int b = i >> 8, p4 = i & 255;
        float4 v = reinterpret_cast<const float4*>(
            x + (size_t)b * C_ * N_ + (size_t)c * N_)[p4];
        s  += v.x + v.y + v.z + v.w;
        ss += v.x * v.x + v.y * v.y + v.z * v.z + v.w * v.w;
    }
    __shared__ float sh1[256], sh2[256];
    sh1[tid] = s; sh2[tid] = ss;
    __syncthreads();
    for (int k = 128; k > 0; k >>= 1) {
        if (tid < k) { sh1[tid] += sh1[tid + k]; sh2[tid] += sh2[tid + k]; }
        __syncthreads();
    }
    if (tid == 0) {
        const float inv_n = 1.0f / (float)(B_ * N_);
        float mean = sh1[0] * inv_n;
        float var  = sh2[0] * inv_n - mean * mean;
        g_mean[c] = mean;
        g_rstd[c] = rsqrtf(var + 1e-5f);
    }
}

// ------- BN apply + transpose [B,C,N] -> [B,N,C] (fp16 out) --------------
__global__ void bn_apply_transpose_kernel(const float* __restrict__ x,
                                          const float* __restrict__ gamma,
                                          const float* __restrict__ beta) {
    __shared__ float sh[32][33];
    const int b = blockIdx.z, c0 = blockIdx.y * 32, n0 = blockIdx.x * 32;
    const int tx = threadIdx.x, ty = threadIdx.y;
    const int c = c0 + ty;
    float v = x[(size_t)b * C_ * N_ + (size_t)c * N_ + (n0 + tx)];
    v = (v - g_mean[c]) * g_rstd[c] * gamma[c] + beta[c];
    sh[ty][tx] = v;
    __syncthreads();
    g_t[((size_t)b * N_ + (n0 + ty)) * C_ + (c0 + tx)] = __float2half_rn(sh[tx][ty]);
}

// ---------------- launch ----------------
extern "C" void kernel_launch(void* const* d_in, const int* in_sizes, int n_in,
                              void* d_out, int out_size) {
    const float* x      = (const float*)d_in[0];
    const float* gamma  = (const float*)d_in[1];
    const float* beta   = (const float*)d_in[2];
    const float* W_kqv  = (const float*)d_in[3];
    const float* b_kqv  = (const float*)d_in[4];
    const float* W_proj = (const float*)d_in[5];
    const float* b_proj = (const float*)d_in[6];
    float* out = (float*)d_out;

    cudaFuncSetAttribute(tc_gemm<MODE_KQV >, cudaFuncAttributeMaxDynamicSharedMemorySize, SMEM_DYN);
    cudaFuncSetAttribute(tc_gemm<MODE_QK  >, cudaFuncAttributeMaxDynamicSharedMemorySize, SMEM_DYN);
    cudaFuncSetAttribute(tc_gemm<MODE_AV  >, cudaFuncAttributeMaxDynamicSharedMemorySize, SMEM_DYN);
    cudaFuncSetAttribute(tc_gemm<MODE_PROJ>, cudaFuncAttributeMaxDynamicSharedMemorySize, SMEM_DYN);

    void *pt, *pkqv, *ps, *pvt, *po, *pwk, *pwp;
    cudaGetSymbolAddress(&pt,   g_t);
    cudaGetSymbolAddress(&pkqv, g_kqv);
    cudaGetSymbolAddress(&ps,   g_s);
    cudaGetSymbolAddress(&pvt,  g_vt);
    cudaGetSymbolAddress(&po,   g_o);
    cudaGetSymbolAddress(&pwk,  g_wk);
    cudaGetSymbolAddress(&pwp,  g_wp);
    __half* t   = (__half*)pt;
    __half* kqv = (__half*)pkqv;
    __half* s   = (__half*)ps;
    __half* vt  = (__half*)pvt;
    __half* o   = (__half*)po;
    __half* wk  = (__half*)pwk;
    __half* wp  = (__half*)pwp;

    bn_stats_kernel<<<C_, 256>>>(x);
    cvt_w_kernel<<<(C3_ * C_) / 256, 256>>>(W_kqv, W_proj);
    bn_apply_transpose_kernel<<<dim3(N_ / 32, C_ / 32, B_), dim3(32, 32)>>>(x, gamma, beta);

    // kqv: Q,K -> kqv; V tile (x=2) -> g_vt transposed
    tc_gemm<MODE_KQV><<<dim3(C3_ / 256, MTOT / 128, 1), NT, SMEM_DYN>>>(
        t, wk, b_kqv, kqv, nullptr, C_, C_, C_, C3_, 0L, 0L, 0L, 1.0f);

    // s = q @ k^T / 16 per batch + softmax partials
    tc_gemm<MODE_QK><<<dim3(N_ / 256, N_ / 128, B_), NT, SMEM_DYN>>>(
        kqv, kqv + 256, nullptr, s, nullptr, C_, C3_, C3_, N_,
        (long)N_ * C3_, (long)N_ * C3_, (long)N_ * N_, 0.0625f);

    reduce_ml_kernel<<<MTOT / 256, 256>>>();

    // o = softmax(s) @ v : exp in A-loader; B = vt, full C in one n-tile
    tc_gemm<MODE_AV><<<dim3(C_ / 256, N_ / 128, B_), NT, SMEM_DYN>>>(
        s, vt, nullptr, o, nullptr, N_, N_, N_, C_,
        (long)N_ * N_, (long)C_ * N_, (long)N_ * C_, 1.0f);

    // fused proj: out[b,c,n] = (o @ W_proj^T + b_proj)^T + x
    tc_gemm<MODE_PROJ><<<dim3(C_ / 256, MTOT / 128, 1), NT, SMEM_DYN>>>(
        o, wp, b_proj, out, x, C_, C_, C_, 0, 0L, 0L, 0L, 1.0f);
}

// round 11
// speedup vs baseline: 1.0216x; 1.0216x over previous
#include <cuda_runtime.h>
#include <cuda_fp16.h>
#include <math.h>
#include <stdint.h>

// ---------------- problem constants ----------------
constexpr int B_   = 32;
constexpr int C_   = 256;
constexpr int N_   = 1024;
constexpr int C3_  = 768;
constexpr int MTOT = B_ * N_;   // 32768

// ---------------- scratch (half intermediates) ----------------
__device__ float  g_mean[C_];
__device__ float  g_rstd[C_];
__device__ __half g_t  [(size_t)MTOT * C_];    // [B,N,C]
__device__ __half g_kqv[(size_t)MTOT * C3_];   // [B,N,3C] (Q,K used)
__device__ __half g_s  [(size_t)B_ * N_ * N_]; // [B,N,N] scaled scores
__device__ __half g_vt [(size_t)B_ * C_ * N_]; // [B,C,N] V^T
__device__ __half g_o  [(size_t)MTOT * C_];    // [B,N,C]
__device__ __half g_wk [(size_t)C3_ * C_];     // W_kqv fp16
__device__ __half g_wp [(size_t)C_ * C_];      // W_proj fp16
__device__ float  g_pm [(size_t)B_ * 8 * N_];  // per-tile row max
__device__ float  g_pl [(size_t)B_ * 8 * N_];  // per-tile row expsum
__device__ float2 g_ml [(size_t)B_ * N_];      // (rowmax, 1/rowsum)

// ---------------- PTX helpers ----------------
__device__ __forceinline__ uint32_t smem_u32(const void* p) {
    return (uint32_t)__cvta_generic_to_shared(p);
}
__device__ __forceinline__ void mma_fp16(float c[4], const uint32_t a[4], const uint32_t b[2]) {
    asm volatile(
        "mma.sync.aligned.m16n8k16.row.col.f32.f16.f16.f32 "
        "{%0,%1,%2,%3}, {%4,%5,%6,%7}, {%8,%9}, {%0,%1,%2,%3};"
        : "+f"(c[0]), "+f"(c[1]), "+f"(c[2]), "+f"(c[3])
        : "r"(a[0]), "r"(a[1]), "r"(a[2]), "r"(a[3]), "r"(b[0]), "r"(b[1]));
}
#define LDSM_X4(r0, r1, r2, r3, addr) \
    asm volatile("ldmatrix.sync.aligned.m8n8.x4.shared.b16 {%0,%1,%2,%3}, [%4];" \
        : "=r"(r0), "=r"(r1), "=r"(r2), "=r"(r3) : "r"(addr))
#define CP_ASYNC16(dst, src) \
    asm volatile("cp.async.cg.shared.global [%0], [%1], 16;" :: "r"(dst), "l"(src))
#define CP_ASYNC_COMMIT() asm volatile("cp.async.commit_group;" ::: "memory")
#define CP_ASYNC_WAIT(n)  asm volatile("cp.async.wait_group %0;" :: "n"(n) : "memory")

// ---------------- fused fp16 GEMM family (fp32 accumulate) ----------------
// C = alpha * A * B^T; A [M,K] halves (lda), B [N,K] halves (ldb).
// CTA 128x128, K-chunk 64 halves, 256 thr = 2(M)x4(N) warps, warp 64x32.
// 3-stage cp.async pipe, prefetch distance 2, one barrier per chunk.
constexpr int MODE_KQV  = 0;
constexpr int MODE_QK   = 1;
constexpr int MODE_AV   = 2;
constexpr int MODE_PROJ = 3;

constexpr int NT          = 256;
constexpr int ROW_B       = 144;                 // padded row stride (bytes)
constexpr int TILE_BYTES  = 128 * ROW_B;         // 18432
constexpr int STAGE_BYTES = 2 * TILE_BYTES;      // 36864
constexpr int SMEM_DYN    = 3 * STAGE_BYTES;     // 110592 (2 CTAs/SM)

template <int MODE>
__global__ __launch_bounds__(NT, 2)
void tc_gemm(const __half* __restrict__ A, const __half* __restrict__ Bm,
             const float* __restrict__ bias, void* __restrict__ Cm,
             const void* __restrict__ P0,
             int K, int lda, int ldb, int ldc,
             long sA, long sB, long sC, float alpha) {
    extern __shared__ float sm[];

    const int tid  = threadIdx.x;
    const int lane = tid & 31;
    const int warp = tid >> 5;
    const int wm   = warp & 1;          // 0..1 (M)
    const int wn   = warp >> 1;         // 0..3 (N)
    const int g    = lane >> 2;
    const int q    = lane & 3;

    const int m0 = blockIdx.y * 128;
    const int n0 = blockIdx.x * 128;
    const __half* Ab = A  + (size_t)blockIdx.z * sA;
    const __half* Bb = Bm + (size_t)blockIdx.z * sB;

    const uint32_t smb = smem_u32(sm);

    const uint32_t a_lo =
        (uint32_t)((wm * 64 + (lane & 15)) * ROW_B + (lane >> 4) * 16);
    const uint32_t b_lo =
        (uint32_t)((wn * 32 + ((lane >> 4) & 1) * 8 + (lane & 7)) * ROW_B +
                   ((lane >> 3) & 1) * 16);

    auto load_stage = [&](int slot, int kc) {
        const uint32_t abase = smb + slot * STAGE_BYTES;
        const uint32_t bbase = abase + TILE_BYTES;
        if (MODE != MODE_AV) {
            const __half* Asrc = Ab + (size_t)m0 * lda + kc * 64;
            #pragma unroll
            for (int j = 0; j < 4; j++) {
                int i = tid + j * NT;
                int row = i >> 3, kg = i & 7;
                CP_ASYNC16(abase + (uint32_t)(row * ROW_B + kg * 16),
                           Asrc + (size_t)row * lda + kg * 8);
            }
        }
        const __half* Bsrc = Bb + (size_t)n0 * ldb + kc * 64;
        #pragma unroll
        for (int j = 0; j < 4; j++) {
            int i = tid + j * NT;
            int row = i >> 3, kg = i & 7;
            CP_ASYNC16(bbase + (uint32_t)(row * ROW_B + kg * 16),
                       Bsrc + (size_t)row * ldb + kg * 8);
        }
        CP_ASYNC_COMMIT();
    };

    // AV: A (scores) via LDG -> exp -> half -> STS
    uint4  pend[4];
    float2 mlv[4];
    if (MODE == MODE_AV) {
        #pragma unroll
        for (int j = 0; j < 4; j++) {
            int row = (tid + j * NT) >> 3;
            mlv[j] = g_ml[(size_t)blockIdx.z * N_ + m0 + row];
        }
    }
    auto ldgA = [&](int kc) {
        #pragma unroll
        for (int j = 0; j < 4; j++) {
            int i = tid + j * NT;
            int row = i >> 3, kg = i & 7;
            pend[j] = *reinterpret_cast<const uint4*>(
                Ab + (size_t)(m0 + row) * lda + kc * 64 + kg * 8);
        }
    };
    auto stsA = [&](int slot) {
        #pragma unroll
        for (int j = 0; j < 4; j++) {
            int i = tid + j * NT;
            int row = i >> 3, kg = i & 7;
            const float m = mlv[j].x, il = mlv[j].y;
            const __half2* h = reinterpret_cast<const __half2*>(&pend[j]);
            uint4 outv;
            __half2* ho = reinterpret_cast<__half2*>(&outv);
            #pragma unroll
            for (int p = 0; p < 4; p++) {
                float2 f = __half22float2(h[p]);
                f.x = __expf(f.x - m) * il;
                f.y = __expf(f.y - m) * il;
                ho[p] = __float22half2_rn(f);
            }
            *reinterpret_cast<uint4*>(
                reinterpret_cast<char*>(sm) + slot * STAGE_BYTES +
                row * ROW_B + kg * 16) = outv;
        }
    };

    float acc[4][4][4] = {};
    const int nk = K >> 6;               // K-chunks of 64

    if (MODE == MODE_AV) { ldgA(0); stsA(0); }
    load_stage(0, 0);
    load_stage(1, 1);

    for (int ks = 0; ks < nk; ks++) {
        CP_ASYNC_WAIT(1);
        __syncthreads();
        if (MODE == MODE_AV) { if (ks + 1 < nk) ldgA(ks + 1); }
        if (ks + 2 < nk) load_stage((ks + 2) % 3, ks + 2);
        else             CP_ASYNC_COMMIT();

        const uint32_t abase = smb + (ks % 3) * STAGE_BYTES;
        const uint32_t bbase = abase + TILE_BYTES;

        #pragma unroll
        for (int kk = 0; kk < 4; kk++) {
            uint32_t af[4][4], bf[4][2];
            #pragma unroll
            for (int tm = 0; tm < 4; tm++) {
                LDSM_X4(af[tm][0], af[tm][1], af[tm][2], af[tm][3],
                        abase + a_lo + (uint32_t)(tm * 16 * ROW_B + kk * 32));
            }
            #pragma unroll
            for (int tnp = 0; tnp < 2; tnp++) {
                LDSM_X4(bf[2 * tnp][0], bf[2 * tnp][1], bf[2 * tnp + 1][0], bf[2 * tnp + 1][1],
                        bbase + b_lo + (uint32_t)(tnp * 16 * ROW_B + kk * 32));
            }
            #pragma unroll
            for (int tm = 0; tm < 4; tm++)
                #pragma unroll
                for (int tn = 0; tn < 4; tn++)
                    mma_fp16(acc[tm][tn], af[tm], bf[tn]);
        }
        if (MODE == MODE_AV) { if (ks + 1 < nk) stsA((ks + 1) % 3); }
    }

    // ---------------- epilogues ----------------
    const bool transout = (MODE == MODE_PROJ) || (MODE == MODE_KQV && n0 >= 512);
    if (transout) {
        // acc^T via smem laid out [c][r] (stride 68 -> 16B-aligned quads,
        // conflict-free STS), then float4 LDS + vector global I/O.
        __syncthreads();
        float* ws = sm + warp * (32 * 68);   // 8 warps x 8704 B = 69632 <= SMEM
        #pragma unroll
        for (int tm = 0; tm < 4; tm++) {
            #pragma unroll
            for (int tn = 0; tn < 4; tn++) {
                const int r  = tm * 16 + g;
                const int cb = tn * 8 + 2 * q;
                float b0 = __ldg(&bias[n0 + wn * 32 + cb]);
                float b1 = __ldg(&bias[n0 + wn * 32 + cb + 1]);
                ws[cb * 68 + r]           = acc[tm][tn][0] * alpha + b0;
                ws[(cb + 1) * 68 + r]     = acc[tm][tn][1] * alpha + b1;
                ws[cb * 68 + r + 8]       = acc[tm][tn][2] * alpha + b0;
                ws[(cb + 1) * 68 + r + 8] = acc[tm][tn][3] * alpha + b1;
            }
        }
        __syncwarp();
        const int b     = m0 >> 10;
        const int nbase = (m0 & 1023) + wm * 64;
        const int rq    = lane & 15;         // quad index along r (n)
        #pragma unroll
        for (int i = 0; i < 16; i++) {
            const int c = i * 2 + (lane >> 4);
            float4 v = *reinterpret_cast<float4*>(&ws[c * 68 + rq * 4]);
            if (MODE == MODE_PROJ) {
                const int cg = n0 + wn * 32 + c;
                const size_t o0 = (((size_t)(b * C_ + cg)) << 10) + nbase + rq * 4;
                float4 xv = __ldcs(reinterpret_cast<const float4*>((const float*)P0 + o0));
                v.x += xv.x; v.y += xv.y; v.z += xv.z; v.w += xv.w;
                __stcs(reinterpret_cast<float4*>((float*)Cm + o0), v);
            } else {
                const int cg = (n0 - 512) + wn * 32 + c;
                const size_t o0 = (((size_t)(b * C_ + cg)) << 10) + nbase + rq * 4;
                __half2 h0 = __floats2half2_rn(v.x, v.y);
                __half2 h1 = __floats2half2_rn(v.z, v.w);
                uint2 pk;
                pk.x = *reinterpret_cast<uint32_t*>(&h0);
                pk.y = *reinterpret_cast<uint32_t*>(&h1);
                *reinterpret_cast<uint2*>(&g_vt[o0]) = pk;
            }
        }
        return;
    }

    // standard store (half output)
    {
        __half* Cb = (__half*)Cm + (size_t)blockIdx.z * sC;
        #pragma unroll
        for (int tm = 0; tm < 4; tm++) {
            const int row = m0 + wm * 64 + tm * 16 + g;
            #pragma unroll
            for (int tn = 0; tn < 4; tn++) {
                const int col = n0 + wn * 32 + tn * 8 + 2 * q;
                float b0 = 0.f, b1 = 0.f;
                if (MODE == MODE_KQV) { b0 = __ldg(&bias[col]); b1 = __ldg(&bias[col + 1]); }
                __half2 v0 = __floats2half2_rn(acc[tm][tn][0] * alpha + b0,
                                               acc[tm][tn][1] * alpha + b1);
                __half2 v1 = __floats2half2_rn(acc[tm][tn][2] * alpha + b0,
                                               acc[tm][tn][3] * alpha + b1);
                *reinterpret_cast<__half2*>(&Cb[(size_t)row * ldc + col])       = v0;
                *reinterpret_cast<__half2*>(&Cb[(size_t)(row + 8) * ldc + col]) = v1;
            }
        }
    }

    if (MODE == MODE_QK) {
        float* redm = sm;          // [4][128]
        float* redl = sm + 512;    // [4][128]
        __syncthreads();

        #pragma unroll
        for (int tm = 0; tm < 4; tm++) {
            float mx0 = -1e30f, mx1 = -1e30f;
            #pragma unroll
            for (int tn = 0; tn < 4; tn++) {
                mx0 = fmaxf(mx0, fmaxf(acc[tm][tn][0], acc[tm][tn][1]));
                mx1 = fmaxf(mx1, fmaxf(acc[tm][tn][2], acc[tm][tn][3]));
            }
            mx0 = fmaxf(mx0, __shfl_xor_sync(~0u, mx0, 1));
            mx0 = fmaxf(mx0, __shfl_xor_sync(~0u, mx0, 2));
            mx1 = fmaxf(mx1, __shfl_xor_sync(~0u, mx1, 1));
            mx1 = fmaxf(mx1, __shfl_xor_sync(~0u, mx1, 2));
            if (q == 0) {
                redm[wn * 128 + wm * 64 + tm * 16 + g]     = mx0 * alpha;
                redm[wn * 128 + wm * 64 + tm * 16 + g + 8] = mx1 * alpha;
            }
        }
        __syncthreads();
        #pragma unroll
        for (int tm = 0; tm < 4; tm++) {
            const int r0 = wm * 64 + tm * 16 + g, r1 = r0 + 8;
            float t0 = fmaxf(fmaxf(redm[r0], redm[128 + r0]),
                             fmaxf(redm[256 + r0], redm[384 + r0]));
            float t1 = fmaxf(fmaxf(redm[r1], redm[128 + r1]),
                             fmaxf(redm[256 + r1], redm[384 + r1]));
            float s0 = 0.f, s1 = 0.f;
            #pragma unroll
            for (int tn = 0; tn < 4; tn++) {
                s0 += __expf(acc[tm][tn][0] * alpha - t0);
                s0 += __expf(acc[tm][tn][1] * alpha - t0);
                s1 += __expf(acc[tm][tn][2] * alpha - t1);
                s1 += __expf(acc[tm][tn][3] * alpha - t1);
            }
            s0 += __shfl_xor_sync(~0u, s0, 1);
            s0 += __shfl_xor_sync(~0u, s0, 2);
            s1 += __shfl_xor_sync(~0u, s1, 1);
            s1 += __shfl_xor_sync(~0u, s1, 2);
            if (q == 0) { redl[wn * 128 + r0] = s0; redl[wn * 128 + r1] = s1; }
        }
        __syncthreads();
        if (tid < 128) {
            float m = fmaxf(fmaxf(redm[tid], redm[128 + tid]),
                            fmaxf(redm[256 + tid], redm[384 + tid]));
            float l = redl[tid] + redl[128 + tid] + redl[256 + tid] + redl[384 + tid];
            const size_t pi = ((size_t)blockIdx.z * 8 + blockIdx.x) * N_ + m0 + tid;
            g_pm[pi] = m;
            g_pl[pi] = l;
        }
    }
}

// ---------------- combine partials -> (rowmax, 1/rowsum) -----------------
__global__ void reduce_ml_kernel() {
    const int idx = blockIdx.x * 256 + threadIdx.x;
    const int b = idx >> 10, row = idx & 1023;
    float m = -1e30f;
    #pragma unroll
    for (int t = 0; t < 8; t++)
        m = fmaxf(m, g_pm[((size_t)b * 8 + t) * N_ + row]);
    float l = 0.f;
    #pragma unroll
    for (int t = 0; t < 8; t++) {
        const size_t i = ((size_t)b * 8 + t) * N_ + row;
        l += g_pl[i] * __expf(g_pm[i] - m);
    }
    g_ml[(size_t)b * N_ + row] = make_float2(m, 1.0f / l);
}

// ---------------- BN stats (float4) + fused weight conversion -------------
__global__ void bn_stats_kernel(const float* __restrict__ x,
                                const float* __restrict__ wk,
                                const float* __restrict__ wp) {
    const int c = blockIdx.x, tid = threadIdx.x;

    // fused fp16 weight conversion (independent work, 256 blocks x 256 thr)
    const int gidx = c * 256 + tid;                 // 0..65535
    #pragma unroll
    for (int i = gidx; i < C3_ * C_; i += 65536) g_wk[i] = __float2half_rn(wk[i]);
    g_wp[gidx] = __float2half_rn(wp[gidx]);

    float s = 0.f, ss = 0.f;
    const int NP4 = N_ / 4;   // 256
    for (int i = tid; i < B_ * NP4; i += 256) {
        int b = i >> 8, p4 = i & 255;
        float4 v = reinterpret_cast<const float4*>(
            x + (size_t)b * C_ * N_ + (size_t)c * N_)[p4];
        s  += v.x + v.y + v.z + v.w;
        ss += v.x * v.x + v.y * v.y + v.z * v.z + v.w * v.w;
    }
    __shared__ float sh1[256], sh2[256];
    sh1[tid] = s; sh2[tid] = ss;
    __syncthreads();
    for (int k = 128; k > 0; k >>= 1) {
        if (tid < k) { sh1[tid] += sh1[tid + k]; sh2[tid] += sh2[tid + k]; }
        __syncthreads();
    }
    if (tid == 0) {
        const float inv_n = 1.0f / (float)(B_ * N_);
        float mean = sh1[0] * inv_n;
        float var  = sh2[0] * inv_n - mean * mean;
        g_mean[c] = mean;
        g_rstd[c] = rsqrtf(var + 1e-5f);
    }
}

// ------- BN apply + transpose [B,C,N] -> [B,N,C] (fp16 out) --------------
__global__ void bn_apply_transpose_kernel(const float* __restrict__ x,
                                          const float* __restrict__ gamma,
                                          const float* __restrict__ beta) {
    __shared__ float sh[32][33];
    const int b = blockIdx.z, c0 = blockIdx.y * 32, n0 = blockIdx.x * 32;
    const int tx = threadIdx.x, ty = threadIdx.y;
    const int c = c0 + ty;
    float v = x[(size_t)b * C_ * N_ + (size_t)c * N_ + (n0 + tx)];
    v = (v - g_mean[c]) * g_rstd[c] * gamma[c] + beta[c];
    sh[ty][tx] = v;
    __syncthreads();
    g_t[((size_t)b * N_ + (n0 + ty)) * C_ + (c0 + tx)] = __float2half_rn(sh[tx][ty]);
}

// ---------------- launch ----------------
extern "C" void kernel_launch(void* const* d_in, const int* in_sizes, int n_in,
                              void* d_out, int out_size) {
    const float* x      = (const float*)d_in[0];
    const float* gamma  = (const float*)d_in[1];
    const float* beta   = (const float*)d_in[2];
    const float* W_kqv  = (const float*)d_in[3];
    const float* b_kqv  = (const float*)d_in[4];
    const float* W_proj = (const float*)d_in[5];
    const float* b_proj = (const float*)d_in[6];
    float* out = (float*)d_out;

    cudaFuncSetAttribute(tc_gemm<MODE_KQV >, cudaFuncAttributeMaxDynamicSharedMemorySize, SMEM_DYN);
    cudaFuncSetAttribute(tc_gemm<MODE_QK  >, cudaFuncAttributeMaxDynamicSharedMemorySize, SMEM_DYN);
    cudaFuncSetAttribute(tc_gemm<MODE_AV  >, cudaFuncAttributeMaxDynamicSharedMemorySize, SMEM_DYN);
    cudaFuncSetAttribute(tc_gemm<MODE_PROJ>, cudaFuncAttributeMaxDynamicSharedMemorySize, SMEM_DYN);

    void *pt, *pkqv, *ps, *pvt, *po, *pwk, *pwp;
    cudaGetSymbolAddress(&pt,   g_t);
    cudaGetSymbolAddress(&pkqv, g_kqv);
    cudaGetSymbolAddress(&ps,   g_s);
    cudaGetSymbolAddress(&pvt,  g_vt);
    cudaGetSymbolAddress(&po,   g_o);
    cudaGetSymbolAddress(&pwk,  g_wk);
    cudaGetSymbolAddress(&pwp,  g_wp);
    __half* t   = (__half*)pt;
    __half* kqv = (__half*)pkqv;
    __half* s   = (__half*)ps;
    __half* vt  = (__half*)pvt;
    __half* o   = (__half*)po;
    __half* wk  = (__half*)pwk;
    __half* wp  = (__half*)pwp;

    bn_stats_kernel<<<C_, 256>>>(x, W_kqv, W_proj);
    bn_apply_transpose_kernel<<<dim3(N_ / 32, C_ / 32, B_), dim3(32, 32)>>>(x, gamma, beta);

    // kqv: Q,K -> kqv; V tiles (x>=4) -> g_vt transposed
    tc_gemm<MODE_KQV><<<dim3(C3_ / 128, MTOT / 128, 1), NT, SMEM_DYN>>>(
        t, wk, b_kqv, kqv, nullptr, C_, C_, C_, C3_, 0L, 0L, 0L, 1.0f);

    // s = q @ k^T / 16 per batch + softmax partials
    tc_gemm<MODE_QK><<<dim3(N_ / 128, N_ / 128, B_), NT, SMEM_DYN>>>(
        kqv, kqv + 256, nullptr, s, nullptr, C_, C3_, C3_, N_,
        (long)N_ * C3_, (long)N_ * C3_, (long)N_ * N_, 0.0625f);

    reduce_ml_kernel<<<MTOT / 256, 256>>>();

    // o = softmax(s) @ v : exp in A-loader; B = vt
    tc_gemm<MODE_AV><<<dim3(C_ / 128, N_ / 128, B_), NT, SMEM_DYN>>>(
        s, vt, nullptr, o, nullptr, N_, N_, N_, C_,
        (long)N_ * N_, (long)C_ * N_, (long)N_ * C_, 1.0f);

    // fused proj: out[b,c,n] = (o @ W_proj^T + b_proj)^T + x
    tc_gemm<MODE_PROJ><<<dim3(C_ / 128, MTOT / 128, 1), NT, SMEM_DYN>>>(
        o, wp, b_proj, out, x, C_, C_, C_, 0, 0L, 0L, 0L, 1.0f);
}

// round 12
// speedup vs baseline: 1.0649x; 1.0424x over previous
#include <cuda_runtime.h>
#include <cuda_fp16.h>
#include <math.h>
#include <stdint.h>

// ---------------- problem constants ----------------
constexpr int B_   = 32;
constexpr int C_   = 256;
constexpr int N_   = 1024;
constexpr int C3_  = 768;
constexpr int MTOT = B_ * N_;   // 32768

// ---------------- scratch (half intermediates) ----------------
__device__ float  g_mean[C_];
__device__ float  g_rstd[C_];
__device__ __half g_t  [(size_t)MTOT * C_];    // [B,N,C]
__device__ __half g_kqv[(size_t)MTOT * C3_];   // [B,N,3C] (Q,K used)
__device__ __half g_s  [(size_t)B_ * N_ * N_]; // [B,N,N] scaled scores
__device__ __half g_vt [(size_t)B_ * C_ * N_]; // [B,C,N] V^T
__device__ __half g_o  [(size_t)MTOT * C_];    // [B,N,C]
__device__ __half g_wk [(size_t)C3_ * C_];     // W_kqv fp16
__device__ __half g_wp [(size_t)C_ * C_];      // W_proj fp16
__device__ float  g_pl [(size_t)B_ * 8 * N_];  // per-tile row expsum
__device__ float  g_il [(size_t)B_ * N_];      // 1/rowsum

// ---------------- PTX helpers ----------------
__device__ __forceinline__ uint32_t smem_u32(const void* p) {
    return (uint32_t)__cvta_generic_to_shared(p);
}
__device__ __forceinline__ void mma_fp16(float c[4], const uint32_t a[4], const uint32_t b[2]) {
    asm volatile(
        "mma.sync.aligned.m16n8k16.row.col.f32.f16.f16.f32 "
        "{%0,%1,%2,%3}, {%4,%5,%6,%7}, {%8,%9}, {%0,%1,%2,%3};"
        : "+f"(c[0]), "+f"(c[1]), "+f"(c[2]), "+f"(c[3])
        : "r"(a[0]), "r"(a[1]), "r"(a[2]), "r"(a[3]), "r"(b[0]), "r"(b[1]));
}
#define LDSM_X4(r0, r1, r2, r3, addr) \
    asm volatile("ldmatrix.sync.aligned.m8n8.x4.shared.b16 {%0,%1,%2,%3}, [%4];" \
        : "=r"(r0), "=r"(r1), "=r"(r2), "=r"(r3) : "r"(addr))
#define CP_ASYNC16(dst, src) \
    asm volatile("cp.async.cg.shared.global [%0], [%1], 16;" :: "r"(dst), "l"(src))
#define CP_ASYNC_COMMIT() asm volatile("cp.async.commit_group;" ::: "memory")
#define CP_ASYNC_WAIT(n)  asm volatile("cp.async.wait_group %0;" :: "n"(n) : "memory")

// ---------------- fused fp16 GEMM family (fp32 accumulate) ----------------
// C = alpha * A * B^T; A [M,K] halves (lda), B [N,K] halves (ldb).
// CTA 128x128, K-chunk 64 halves, 256 thr = 2(M)x4(N) warps, warp 64x32.
// 3-stage cp.async pipe, prefetch distance 2, one barrier per chunk.
constexpr int MODE_KQV  = 0;
constexpr int MODE_QK   = 1;
constexpr int MODE_AV   = 2;
constexpr int MODE_PROJ = 3;

constexpr int NT          = 256;
constexpr int ROW_B       = 144;                 // padded row stride (bytes)
constexpr int TILE_BYTES  = 128 * ROW_B;         // 18432
constexpr int STAGE_BYTES = 2 * TILE_BYTES;      // 36864
constexpr int SMEM_DYN    = 3 * STAGE_BYTES;     // 110592 (2 CTAs/SM)

template <int MODE>
__global__ __launch_bounds__(NT, 2)
void tc_gemm(const __half* __restrict__ A, const __half* __restrict__ Bm,
             const float* __restrict__ bias, void* __restrict__ Cm,
             const void* __restrict__ P0,
             int K, int lda, int ldb, int ldc,
             long sA, long sB, long sC, float alpha) {
    extern __shared__ float sm[];

    const int tid  = threadIdx.x;
    const int lane = tid & 31;
    const int warp = tid >> 5;
    const int wm   = warp & 1;          // 0..1 (M)
    const int wn   = warp >> 1;         // 0..3 (N)
    const int g    = lane >> 2;
    const int q    = lane & 3;

    const int m0 = blockIdx.y * 128;
    const int n0 = blockIdx.x * 128;
    const __half* Ab = A  + (size_t)blockIdx.z * sA;
    const __half* Bb = Bm + (size_t)blockIdx.z * sB;

    const uint32_t smb = smem_u32(sm);

    const uint32_t a_lo =
        (uint32_t)((wm * 64 + (lane & 15)) * ROW_B + (lane >> 4) * 16);
    const uint32_t b_lo =
        (uint32_t)((wn * 32 + ((lane >> 4) & 1) * 8 + (lane & 7)) * ROW_B +
                   ((lane >> 3) & 1) * 16);

    auto load_stage = [&](int slot, int kc) {
        const uint32_t abase = smb + slot * STAGE_BYTES;
        const uint32_t bbase = abase + TILE_BYTES;
        if (MODE != MODE_AV) {
            const __half* Asrc = Ab + (size_t)m0 * lda + kc * 64;
            #pragma unroll
            for (int j = 0; j < 4; j++) {
                int i = tid + j * NT;
                int row = i >> 3, kg = i & 7;
                CP_ASYNC16(abase + (uint32_t)(row * ROW_B + kg * 16),
                           Asrc + (size_t)row * lda + kg * 8);
            }
        }
        const __half* Bsrc = Bb + (size_t)n0 * ldb + kc * 64;
        #pragma unroll
        for (int j = 0; j < 4; j++) {
            int i = tid + j * NT;
            int row = i >> 3, kg = i & 7;
            CP_ASYNC16(bbase + (uint32_t)(row * ROW_B + kg * 16),
                       Bsrc + (size_t)row * ldb + kg * 8);
        }
        CP_ASYNC_COMMIT();
    };

    // AV: A (scores) via streaming LDG -> exp -> half -> STS
    uint4 pend[4];
    auto ldgA = [&](int kc) {
        #pragma unroll
        for (int j = 0; j < 4; j++) {
            int i = tid + j * NT;
            int row = i >> 3, kg = i & 7;
            pend[j] = __ldcs(reinterpret_cast<const uint4*>(
                Ab + (size_t)(m0 + row) * lda + kc * 64 + kg * 8));
        }
    };
    auto stsA = [&](int slot) {
        #pragma unroll
        for (int j = 0; j < 4; j++) {
            int i = tid + j * NT;
            int row = i >> 3, kg = i & 7;
            const __half2* h = reinterpret_cast<const __half2*>(&pend[j]);
            uint4 outv;
            __half2* ho = reinterpret_cast<__half2*>(&outv);
            #pragma unroll
            for (int p = 0; p < 4; p++) {
                float2 f = __half22float2(h[p]);
                f.x = __expf(f.x);
                f.y = __expf(f.y);
                ho[p] = __float22half2_rn(f);
            }
            *reinterpret_cast<uint4*>(
                reinterpret_cast<char*>(sm) + slot * STAGE_BYTES +
                row * ROW_B + kg * 16) = outv;
        }
    };

    float acc[4][4][4] = {};
    const int nk = K >> 6;               // K-chunks of 64

    if (MODE == MODE_AV) { ldgA(0); stsA(0); }
    load_stage(0, 0);
    load_stage(1, 1);

    for (int ks = 0; ks < nk; ks++) {
        CP_ASYNC_WAIT(1);
        __syncthreads();
        if (MODE == MODE_AV) { if (ks + 1 < nk) ldgA(ks + 1); }
        if (ks + 2 < nk) load_stage((ks + 2) % 3, ks + 2);
        else             CP_ASYNC_COMMIT();

        const uint32_t abase = smb + (ks % 3) * STAGE_BYTES;
        const uint32_t bbase = abase + TILE_BYTES;

        #pragma unroll
        for (int kk = 0; kk < 4; kk++) {
            uint32_t af[4][4], bf[4][2];
            #pragma unroll
            for (int tm = 0; tm < 4; tm++) {
                LDSM_X4(af[tm][0], af[tm][1], af[tm][2], af[tm][3],
                        abase + a_lo + (uint32_t)(tm * 16 * ROW_B + kk * 32));
            }
            #pragma unroll
            for (int tnp = 0; tnp < 2; tnp++) {
                LDSM_X4(bf[2 * tnp][0], bf[2 * tnp][1], bf[2 * tnp + 1][0], bf[2 * tnp + 1][1],
                        bbase + b_lo + (uint32_t)(tnp * 16 * ROW_B + kk * 32));
            }
            #pragma unroll
            for (int tm = 0; tm < 4; tm++)
                #pragma unroll
                for (int tn = 0; tn < 4; tn++)
                    mma_fp16(acc[tm][tn], af[tm], bf[tn]);
        }
        if (MODE == MODE_AV) { if (ks + 1 < nk) stsA((ks + 1) % 3); }
    }

    // ---------------- epilogues ----------------
    const bool transout = (MODE == MODE_PROJ) || (MODE == MODE_KQV && n0 >= 512);
    if (transout) {
        // acc^T via smem [c][r] (stride 68), then float4 LDS + vector I/O.
        __syncthreads();
        float* ws = sm + warp * (32 * 68);
        #pragma unroll
        for (int tm = 0; tm < 4; tm++) {
            #pragma unroll
            for (int tn = 0; tn < 4; tn++) {
                const int r  = tm * 16 + g;
                const int cb = tn * 8 + 2 * q;
                float b0 = __ldg(&bias[n0 + wn * 32 + cb]);
                float b1 = __ldg(&bias[n0 + wn * 32 + cb + 1]);
                ws[cb * 68 + r]           = acc[tm][tn][0] * alpha + b0;
                ws[(cb + 1) * 68 + r]     = acc[tm][tn][1] * alpha + b1;
                ws[cb * 68 + r + 8]       = acc[tm][tn][2] * alpha + b0;
                ws[(cb + 1) * 68 + r + 8] = acc[tm][tn][3] * alpha + b1;
            }
        }
        __syncwarp();
        const int b     = m0 >> 10;
        const int nbase = (m0 & 1023) + wm * 64;
        const int rq    = lane & 15;
        #pragma unroll
        for (int i = 0; i < 16; i++) {
            const int c = i * 2 + (lane >> 4);
            float4 v = *reinterpret_cast<float4*>(&ws[c * 68 + rq * 4]);
            if (MODE == MODE_PROJ) {
                const int cg = n0 + wn * 32 + c;
                const size_t o0 = (((size_t)(b * C_ + cg)) << 10) + nbase + rq * 4;
                float4 xv = __ldcs(reinterpret_cast<const float4*>((const float*)P0 + o0));
                v.x += xv.x; v.y += xv.y; v.z += xv.z; v.w += xv.w;
                __stcs(reinterpret_cast<float4*>((float*)Cm + o0), v);
            } else {
                const int cg = (n0 - 512) + wn * 32 + c;
                const size_t o0 = (((size_t)(b * C_ + cg)) << 10) + nbase + rq * 4;
                __half2 h0 = __floats2half2_rn(v.x, v.y);
                __half2 h1 = __floats2half2_rn(v.z, v.w);
                uint2 pk;
                pk.x = *reinterpret_cast<uint32_t*>(&h0);
                pk.y = *reinterpret_cast<uint32_t*>(&h1);
                *reinterpret_cast<uint2*>(&g_vt[o0]) = pk;
            }
        }
        return;
    }

    // standard store (half output); AV scales rows by 1/l here
    {
        __half* Cb = (__half*)Cm + (size_t)blockIdx.z * sC;
        #pragma unroll
        for (int tm = 0; tm < 4; tm++) {
            const int row = m0 + wm * 64 + tm * 16 + g;
            float a0 = alpha, a1 = alpha;
            if (MODE == MODE_AV) {
                a0 = g_il[(size_t)blockIdx.z * N_ + row];
                a1 = g_il[(size_t)blockIdx.z * N_ + row + 8];
            }
            #pragma unroll
            for (int tn = 0; tn < 4; tn++) {
                const int col = n0 + wn * 32 + tn * 8 + 2 * q;
                float b0 = 0.f, b1 = 0.f;
                if (MODE == MODE_KQV) { b0 = __ldg(&bias[col]); b1 = __ldg(&bias[col + 1]); }
                __half2 v0 = __floats2half2_rn(acc[tm][tn][0] * a0 + b0,
                                               acc[tm][tn][1] * a0 + b1);
                __half2 v1 = __floats2half2_rn(acc[tm][tn][2] * a1 + b0,
                                               acc[tm][tn][3] * a1 + b1);
                *reinterpret_cast<__half2*>(&Cb[(size_t)row * ldc + col])       = v0;
                *reinterpret_cast<__half2*>(&Cb[(size_t)(row + 8) * ldc + col]) = v1;
            }
        }
    }

    if (MODE == MODE_QK) {
        // expsum partials (no max subtraction; |s| <= ~8 so exp is safe)
        float* redl = sm;          // [4][128]
        __syncthreads();
        #pragma unroll
        for (int tm = 0; tm < 4; tm++) {
            float s0 = 0.f, s1 = 0.f;
            #pragma unroll
            for (int tn = 0; tn < 4; tn++) {
                s0 += __expf(acc[tm][tn][0] * alpha);
                s0 += __expf(acc[tm][tn][1] * alpha);
                s1 += __expf(acc[tm][tn][2] * alpha);
                s1 += __expf(acc[tm][tn][3] * alpha);
            }
            s0 += __shfl_xor_sync(~0u, s0, 1);
            s0 += __shfl_xor_sync(~0u, s0, 2);
            s1 += __shfl_xor_sync(~0u, s1, 1);
            s1 += __shfl_xor_sync(~0u, s1, 2);
            if (q == 0) {
                redl[wn * 128 + wm * 64 + tm * 16 + g]     = s0;
                redl[wn * 128 + wm * 64 + tm * 16 + g + 8] = s1;
            }
        }
        __syncthreads();
        if (tid < 128) {
            float l = redl[tid] + redl[128 + tid] + redl[256 + tid] + redl[384 + tid];
            g_pl[((size_t)blockIdx.z * 8 + blockIdx.x) * N_ + m0 + tid] = l;
        }
    }
}

// ---------------- combine partials -> 1/rowsum -----------------
__global__ void reduce_il_kernel() {
    const int idx = blockIdx.x * 256 + threadIdx.x;
    const int b = idx >> 10, row = idx & 1023;
    float l = 0.f;
    #pragma unroll
    for (int t = 0; t < 8; t++)
        l += g_pl[((size_t)b * 8 + t) * N_ + row];
    g_il[(size_t)b * N_ + row] = 1.0f / l;
}

// ---------------- BN stats (float4) + fused weight conversion -------------
__global__ void bn_stats_kernel(const float* __restrict__ x,
                                const float* __restrict__ wk,
                                const float* __restrict__ wp) {
    const int c = blockIdx.x, tid = threadIdx.x;

    const int gidx = c * 256 + tid;                 // 0..65535
    #pragma unroll
    for (int i = gidx; i < C3_ * C_; i += 65536) g_wk[i] = __float2half_rn(wk[i]);
    g_wp[gidx] = __float2half_rn(wp[gidx]);

    float s = 0.f, ss = 0.f;
    const int NP4 = N_ / 4;
    for (int i = tid; i < B_ * NP4; i += 256) {
        int b = i >> 8, p4 = i & 255;
        float4 v = reinterpret_cast<const float4*>(
            x + (size_t)b * C_ * N_ + (size_t)c * N_)[p4];
        s  += v.x + v.y + v.z + v.w;
        ss += v.x * v.x + v.y * v.y + v.z * v.z + v.w * v.w;
    }
    __shared__ float sh1[256], sh2[256];
    sh1[tid] = s; sh2[tid] = ss;
    __syncthreads();
    for (int k = 128; k > 0; k >>= 1) {
        if (tid < k) { sh1[tid] += sh1[tid + k]; sh2[tid] += sh2[tid + k]; }
        __syncthreads();
    }
    if (tid == 0) {
        const float inv_n = 1.0f / (float)(B_ * N_);
        float mean = sh1[0] * inv_n;
        float var  = sh2[0] * inv_n - mean * mean;
        g_mean[c] = mean;
        g_rstd[c] = rsqrtf(var + 1e-5f);
    }
}

// ------- BN apply + transpose [B,C,N] -> [B,N,C] (fp16 out) --------------
__global__ void bn_apply_transpose_kernel(const float* __restrict__ x,
                                          const float* __restrict__ gamma,
                                          const float* __restrict__ beta) {
    __shared__ float sh[32][33];
    const int b = blockIdx.z, c0 = blockIdx.y * 32, n0 = blockIdx.x * 32;
    const int tx = threadIdx.x, ty = threadIdx.y;
    const int c = c0 + ty;
    float v = x[(size_t)b * C_ * N_ + (size_t)c * N_ + (n0 + tx)];
    v = (v - g_mean[c]) * g_rstd[c] * gamma[c] + beta[c];
    sh[ty][tx] = v;
    __syncthreads();
    g_t[((size_t)b * N_ + (n0 + ty)) * C_ + (c0 + tx)] = __float2half_rn(sh[tx][ty]);
}

// ---------------- launch ----------------
extern "C" void kernel_launch(void* const* d_in, const int* in_sizes, int n_in,
                              void* d_out, int out_size) {
    const float* x      = (const float*)d_in[0];
    const float* gamma  = (const float*)d_in[1];
    const float* beta   = (const float*)d_in[2];
    const float* W_kqv  = (const float*)d_in[3];
    const float* b_kqv  = (const float*)d_in[4];
    const float* W_proj = (const float*)d_in[5];
    const float* b_proj = (const float*)d_in[6];
    float* out = (float*)d_out;

    cudaFuncSetAttribute(tc_gemm<MODE_KQV >, cudaFuncAttributeMaxDynamicSharedMemorySize, SMEM_DYN);
    cudaFuncSetAttribute(tc_gemm<MODE_QK  >, cudaFuncAttributeMaxDynamicSharedMemorySize, SMEM_DYN);
    cudaFuncSetAttribute(tc_gemm<MODE_AV  >, cudaFuncAttributeMaxDynamicSharedMemorySize, SMEM_DYN);
    cudaFuncSetAttribute(tc_gemm<MODE_PROJ>, cudaFuncAttributeMaxDynamicSharedMemorySize, SMEM_DYN);

    void *pt, *pkqv, *ps, *pvt, *po, *pwk, *pwp;
    cudaGetSymbolAddress(&pt,   g_t);
    cudaGetSymbolAddress(&pkqv, g_kqv);
    cudaGetSymbolAddress(&ps,   g_s);
    cudaGetSymbolAddress(&pvt,  g_vt);
    cudaGetSymbolAddress(&po,   g_o);
    cudaGetSymbolAddress(&pwk,  g_wk);
    cudaGetSymbolAddress(&pwp,  g_wp);
    __half* t   = (__half*)pt;
    __half* kqv = (__half*)pkqv;
    __half* s   = (__half*)ps;
    __half* vt  = (__half*)pvt;
    __half* o   = (__half*)po;
    __half* wk  = (__half*)pwk;
    __half* wp  = (__half*)pwp;

    bn_stats_kernel<<<C_, 256>>>(x, W_kqv, W_proj);
    bn_apply_transpose_kernel<<<dim3(N_ / 32, C_ / 32, B_), dim3(32, 32)>>>(x, gamma, beta);

    // kqv: Q,K -> kqv; V tiles -> g_vt transposed
    tc_gemm<MODE_KQV><<<dim3(C3_ / 128, MTOT / 128, 1), NT, SMEM_DYN>>>(
        t, wk, b_kqv, kqv, nullptr, C_, C_, C_, C3_, 0L, 0L, 0L, 1.0f);

    // s = q @ k^T / 16 per batch + expsum partials
    tc_gemm<MODE_QK><<<dim3(N_ / 128, N_ / 128, B_), NT, SMEM_DYN>>>(
        kqv, kqv + 256, nullptr, s, nullptr, C_, C3_, C3_, N_,
        (long)N_ * C3_, (long)N_ * C3_, (long)N_ * N_, 0.0625f);

    reduce_il_kernel<<<MTOT / 256, 256>>>();

    // o = exp(s) @ v scaled by 1/l in epilogue
    tc_gemm<MODE_AV><<<dim3(C_ / 128, N_ / 128, B_), NT, SMEM_DYN>>>(
        s, vt, nullptr, o, nullptr, N_, N_, N_, C_,
        (long)N_ * N_, (long)C_ * N_, (long)N_ * C_, 1.0f);

    // fused proj: out[b,c,n] = (o @ W_proj^T + b_proj)^T + x
    tc_gemm<MODE_PROJ><<<dim3(C_ / 128, MTOT / 128, 1), NT, SMEM_DYN>>>(
        o, wp, b_proj, out, x, C_, C_, C_, 0, 0L, 0L, 0L, 1.0f);
}

// round 13
// speedup vs baseline: 1.0922x; 1.0256x over previous
#include <cuda_runtime.h>
#include <cuda_fp16.h>
#include <math.h>
#include <stdint.h>

// ---------------- problem constants ----------------
constexpr int B_   = 32;
constexpr int C_   = 256;
constexpr int N_   = 1024;
constexpr int C3_  = 768;
constexpr int MTOT = B_ * N_;   // 32768

// ---------------- scratch (half intermediates) ----------------
__device__ float  g_mean[C_];
__device__ float  g_rstd[C_];
__device__ __half g_t  [(size_t)MTOT * C_];    // [B,N,C]
__device__ __half g_kqv[(size_t)MTOT * C3_];   // [B,N,3C] (Q,K used)
__device__ __half g_s  [(size_t)B_ * N_ * N_]; // [B,N,N] exp(scores/16)
__device__ __half g_vt [(size_t)B_ * C_ * N_]; // [B,C,N] V^T
__device__ __half g_o  [(size_t)MTOT * C_];    // [B,N,C]
__device__ __half g_wk [(size_t)C3_ * C_];     // W_kqv fp16
__device__ __half g_wp [(size_t)C_ * C_];      // W_proj fp16
__device__ float  g_pl [(size_t)B_ * 8 * N_];  // per-tile row expsum
__device__ float  g_il [(size_t)B_ * N_];      // 1/rowsum

// ---------------- PTX helpers ----------------
__device__ __forceinline__ uint32_t smem_u32(const void* p) {
    return (uint32_t)__cvta_generic_to_shared(p);
}
__device__ __forceinline__ void mma_fp16(float c[4], const uint32_t a[4], const uint32_t b[2]) {
    asm volatile(
        "mma.sync.aligned.m16n8k16.row.col.f32.f16.f16.f32 "
        "{%0,%1,%2,%3}, {%4,%5,%6,%7}, {%8,%9}, {%0,%1,%2,%3};"
        : "+f"(c[0]), "+f"(c[1]), "+f"(c[2]), "+f"(c[3])
        : "r"(a[0]), "r"(a[1]), "r"(a[2]), "r"(a[3]), "r"(b[0]), "r"(b[1]));
}
#define LDSM_X4(r0, r1, r2, r3, addr) \
    asm volatile("ldmatrix.sync.aligned.m8n8.x4.shared.b16 {%0,%1,%2,%3}, [%4];" \
        : "=r"(r0), "=r"(r1), "=r"(r2), "=r"(r3) : "r"(addr))
#define CP_ASYNC16(dst, src) \
    asm volatile("cp.async.cg.shared.global [%0], [%1], 16;" :: "r"(dst), "l"(src))
#define CP_ASYNC_COMMIT() asm volatile("cp.async.commit_group;" ::: "memory")
#define CP_ASYNC_WAIT(n)  asm volatile("cp.async.wait_group %0;" :: "n"(n) : "memory")

// ---------------- fused fp16 GEMM family (fp32 accumulate) ----------------
// C = alpha * A * B^T; A [M,K] halves (lda), B [N,K] halves (ldb).
// CTA 128x128, K-chunk 64 halves, 256 thr = 2(M)x4(N) warps, warp 64x32.
// 3-stage cp.async pipe, prefetch distance 2, one barrier per chunk.
// Modes:
//  KQV : +bias; Q/K -> kqv; V tiles (n0>=512) -> g_vt transposed.
//  QK  : stores exp(acc*alpha) as fp16; accumulates per-tile row expsums.
//  AV  : plain GEMM on exp-scores; rows scaled by g_il (1/sum) in epilogue.
//  PROJ: +bias; transposed store + residual to final fp32 output.
constexpr int MODE_KQV  = 0;
constexpr int MODE_QK   = 1;
constexpr int MODE_AV   = 2;
constexpr int MODE_PROJ = 3;

constexpr int NT          = 256;
constexpr int ROW_B       = 144;                 // padded row stride (bytes)
constexpr int TILE_BYTES  = 128 * ROW_B;         // 18432
constexpr int STAGE_BYTES = 2 * TILE_BYTES;      // 36864
constexpr int SMEM_DYN    = 3 * STAGE_BYTES;     // 110592 (2 CTAs/SM)

template <int MODE>
__global__ __launch_bounds__(NT, 2)
void tc_gemm(const __half* __restrict__ A, const __half* __restrict__ Bm,
             const float* __restrict__ bias, void* __restrict__ Cm,
             const void* __restrict__ P0,
             int K, int lda, int ldb, int ldc,
             long sA, long sB, long sC, float alpha) {
    extern __shared__ float sm[];

    const int tid  = threadIdx.x;
    const int lane = tid & 31;
    const int warp = tid >> 5;
    const int wm   = warp & 1;          // 0..1 (M)
    const int wn   = warp >> 1;         // 0..3 (N)
    const int g    = lane >> 2;
    const int q    = lane & 3;

    const int m0 = blockIdx.y * 128;
    const int n0 = blockIdx.x * 128;
    const __half* Ab = A  + (size_t)blockIdx.z * sA;
    const __half* Bb = Bm + (size_t)blockIdx.z * sB;

    const uint32_t smb = smem_u32(sm);

    const uint32_t a_lo =
        (uint32_t)((wm * 64 + (lane & 15)) * ROW_B + (lane >> 4) * 16);
    const uint32_t b_lo =
        (uint32_t)((wn * 32 + ((lane >> 4) & 1) * 8 + (lane & 7)) * ROW_B +
                   ((lane >> 3) & 1) * 16);

    auto load_stage = [&](int slot, int kc) {
        const uint32_t abase = smb + slot * STAGE_BYTES;
        const uint32_t bbase = abase + TILE_BYTES;
        const __half* Asrc = Ab + (size_t)m0 * lda + kc * 64;
        #pragma unroll
        for (int j = 0; j < 4; j++) {
            int i = tid + j * NT;
            int row = i >> 3, kg = i & 7;
            CP_ASYNC16(abase + (uint32_t)(row * ROW_B + kg * 16),
                       Asrc + (size_t)row * lda + kg * 8);
        }
        const __half* Bsrc = Bb + (size_t)n0 * ldb + kc * 64;
        #pragma unroll
        for (int j = 0; j < 4; j++) {
            int i = tid + j * NT;
            int row = i >> 3, kg = i & 7;
            CP_ASYNC16(bbase + (uint32_t)(row * ROW_B + kg * 16),
                       Bsrc + (size_t)row * ldb + kg * 8);
        }
        CP_ASYNC_COMMIT();
    };

    float acc[4][4][4] = {};
    const int nk = K >> 6;               // K-chunks of 64

    load_stage(0, 0);
    load_stage(1, 1);

    for (int ks = 0; ks < nk; ks++) {
        CP_ASYNC_WAIT(1);
        __syncthreads();
        if (ks + 2 < nk) load_stage((ks + 2) % 3, ks + 2);
        else             CP_ASYNC_COMMIT();

        const uint32_t abase = smb + (ks % 3) * STAGE_BYTES;
        const uint32_t bbase = abase + TILE_BYTES;

        #pragma unroll
        for (int kk = 0; kk < 4; kk++) {
            uint32_t af[4][4], bf[4][2];
            #pragma unroll
            for (int tm = 0; tm < 4; tm++) {
                LDSM_X4(af[tm][0], af[tm][1], af[tm][2], af[tm][3],
                        abase + a_lo + (uint32_t)(tm * 16 * ROW_B + kk * 32));
            }
            #pragma unroll
            for (int tnp = 0; tnp < 2; tnp++) {
                LDSM_X4(bf[2 * tnp][0], bf[2 * tnp][1], bf[2 * tnp + 1][0], bf[2 * tnp + 1][1],
                        bbase + b_lo + (uint32_t)(tnp * 16 * ROW_B + kk * 32));
            }
            #pragma unroll
            for (int tm = 0; tm < 4; tm++)
                #pragma unroll
                for (int tn = 0; tn < 4; tn++)
                    mma_fp16(acc[tm][tn], af[tm], bf[tn]);
        }
    }

    // ---------------- epilogues ----------------
    const bool transout = (MODE == MODE_PROJ) || (MODE == MODE_KQV && n0 >= 512);
    if (transout) {
        // acc^T via smem [c][r] (stride 68), then float4 LDS + vector I/O.
        __syncthreads();
        float* ws = sm + warp * (32 * 68);
        #pragma unroll
        for (int tm = 0; tm < 4; tm++) {
            #pragma unroll
            for (int tn = 0; tn < 4; tn++) {
                const int r  = tm * 16 + g;
                const int cb = tn * 8 + 2 * q;
                float b0 = __ldg(&bias[n0 + wn * 32 + cb]);
                float b1 = __ldg(&bias[n0 + wn * 32 + cb + 1]);
                ws[cb * 68 + r]           = acc[tm][tn][0] * alpha + b0;
                ws[(cb + 1) * 68 + r]     = acc[tm][tn][1] * alpha + b1;
                ws[cb * 68 + r + 8]       = acc[tm][tn][2] * alpha + b0;
                ws[(cb + 1) * 68 + r + 8] = acc[tm][tn][3] * alpha + b1;
            }
        }
        __syncwarp();
        const int b     = m0 >> 10;
        const int nbase = (m0 & 1023) + wm * 64;
        const int rq    = lane & 15;
        #pragma unroll
        for (int i = 0; i < 16; i++) {
            const int c = i * 2 + (lane >> 4);
            float4 v = *reinterpret_cast<float4*>(&ws[c * 68 + rq * 4]);
            if (MODE == MODE_PROJ) {
                const int cg = n0 + wn * 32 + c;
                const size_t o0 = (((size_t)(b * C_ + cg)) << 10) + nbase + rq * 4;
                float4 xv = __ldcs(reinterpret_cast<const float4*>((const float*)P0 + o0));
                v.x += xv.x; v.y += xv.y; v.z += xv.z; v.w += xv.w;
                __stcs(reinterpret_cast<float4*>((float*)Cm + o0), v);
            } else {
                const int cg = (n0 - 512) + wn * 32 + c;
                const size_t o0 = (((size_t)(b * C_ + cg)) << 10) + nbase + rq * 4;
                __half2 h0 = __floats2half2_rn(v.x, v.y);
                __half2 h1 = __floats2half2_rn(v.z, v.w);
                uint2 pk;
                pk.x = *reinterpret_cast<uint32_t*>(&h0);
                pk.y = *reinterpret_cast<uint32_t*>(&h1);
                *reinterpret_cast<uint2*>(&g_vt[o0]) = pk;
            }
        }
        return;
    }

    if (MODE == MODE_QK) {
        // store exp(acc*alpha) as fp16 AND accumulate row expsums (one exp pass)
        __half* Cb = (__half*)Cm + (size_t)blockIdx.z * sC;
        float* redl = sm;          // [4][128]
        __syncthreads();
        #pragma unroll
        for (int tm = 0; tm < 4; tm++) {
            const int row = m0 + wm * 64 + tm * 16 + g;
            float s0 = 0.f, s1 = 0.f;
            #pragma unroll
            for (int tn = 0; tn < 4; tn++) {
                const int col = n0 + wn * 32 + tn * 8 + 2 * q;
                float e0 = __expf(acc[tm][tn][0] * alpha);
                float e1 = __expf(acc[tm][tn][1] * alpha);
                float e2 = __expf(acc[tm][tn][2] * alpha);
                float e3 = __expf(acc[tm][tn][3] * alpha);
                s0 += e0 + e1;
                s1 += e2 + e3;
                __half2 v0 = __floats2half2_rn(e0, e1);
                __half2 v1 = __floats2half2_rn(e2, e3);
                *reinterpret_cast<__half2*>(&Cb[(size_t)row * ldc + col])       = v0;
                *reinterpret_cast<__half2*>(&Cb[(size_t)(row + 8) * ldc + col]) = v1;
            }
            s0 += __shfl_xor_sync(~0u, s0, 1);
            s0 += __shfl_xor_sync(~0u, s0, 2);
            s1 += __shfl_xor_sync(~0u, s1, 1);
            s1 += __shfl_xor_sync(~0u, s1, 2);
            if (q == 0) {
                redl[wn * 128 + wm * 64 + tm * 16 + g]     = s0;
                redl[wn * 128 + wm * 64 + tm * 16 + g + 8] = s1;
            }
        }
        __syncthreads();
        if (tid < 128) {
            float l = redl[tid] + redl[128 + tid] + redl[256 + tid] + redl[384 + tid];
            g_pl[((size_t)blockIdx.z * 8 + blockIdx.x) * N_ + m0 + tid] = l;
        }
        return;
    }

    // standard store (half output); AV scales rows by 1/l
    {
        __half* Cb = (__half*)Cm + (size_t)blockIdx.z * sC;
        #pragma unroll
        for (int tm = 0; tm < 4; tm++) {
            const int row = m0 + wm * 64 + tm * 16 + g;
            float a0 = alpha, a1 = alpha;
            if (MODE == MODE_AV) {
                a0 = g_il[(size_t)blockIdx.z * N_ + row];
                a1 = g_il[(size_t)blockIdx.z * N_ + row + 8];
            }
            #pragma unroll
            for (int tn = 0; tn < 4; tn++) {
                const int col = n0 + wn * 32 + tn * 8 + 2 * q;
                float b0 = 0.f, b1 = 0.f;
                if (MODE == MODE_KQV) { b0 = __ldg(&bias[col]); b1 = __ldg(&bias[col + 1]); }
                __half2 v0 = __floats2half2_rn(acc[tm][tn][0] * a0 + b0,
                                               acc[tm][tn][1] * a0 + b1);
                __half2 v1 = __floats2half2_rn(acc[tm][tn][2] * a1 + b0,
                                               acc[tm][tn][3] * a1 + b1);
                *reinterpret_cast<__half2*>(&Cb[(size_t)row * ldc + col])       = v0;
                *reinterpret_cast<__half2*>(&Cb[(size_t)(row + 8) * ldc + col]) = v1;
            }
        }
    }
}

// ---------------- combine partials -> 1/rowsum -----------------
__global__ void reduce_il_kernel() {
    const int idx = blockIdx.x * 256 + threadIdx.x;
    const int b = idx >> 10, row = idx & 1023;
    float l = 0.f;
    #pragma unroll
    for (int t = 0; t < 8; t++)
        l += g_pl[((size_t)b * 8 + t) * N_ + row];
    g_il[(size_t)b * N_ + row] = 1.0f / l;
}

// ---------------- BN stats (float4) + fused weight conversion -------------
__global__ void bn_stats_kernel(const float* __restrict__ x,
                                const float* __restrict__ wk,
                                const float* __restrict__ wp) {
    const int c = blockIdx.x, tid = threadIdx.x;

    const int gidx = c * 256 + tid;                 // 0..65535
    #pragma unroll
    for (int i = gidx; i < C3_ * C_; i += 65536) g_wk[i] = __float2half_rn(wk[i]);
    g_wp[gidx] = __float2half_rn(wp[gidx]);

    float s = 0.f, ss = 0.f;
    const int NP4 = N_ / 4;
    for (int i = tid; i < B_ * NP4; i += 256) {
        int b = i >> 8, p4 = i & 255;
        float4 v = reinterpret_cast<const float4*>(
            x + (size_t)b * C_ * N_ + (size_t)c * N_)[p4];
        s  += v.x + v.y + v.z + v.w;
        ss += v.x * v.x + v.y * v.y + v.z * v.z + v.w * v.w;
    }
    __shared__ float sh1[256], sh2[256];
    sh1[tid] = s; sh2[tid] = ss;
    __syncthreads();
    for (int k = 128; k > 0; k >>= 1) {
        if (tid < k) { sh1[tid] += sh1[tid + k]; sh2[tid] += sh2[tid + k]; }
        __syncthreads();
    }
    if (tid == 0) {
        const float inv_n = 1.0f / (float)(B_ * N_);
        float mean = sh1[0] * inv_n;
        float var  = sh2[0] * inv_n - mean * mean;
        g_mean[c] = mean;
        g_rstd[c] = rsqrtf(var + 1e-5f);
    }
}

// ------- BN apply + transpose [B,C,N] -> [B,N,C] (fp16 out) --------------
__global__ void bn_apply_transpose_kernel(const float* __restrict__ x,
                                          const float* __restrict__ gamma,
                                          const float* __restrict__ beta) {
    __shared__ float sh[32][33];
    const int b = blockIdx.z, c0 = blockIdx.y * 32, n0 = blockIdx.x * 32;
    const int tx = threadIdx.x, ty = threadIdx.y;
    const int c = c0 + ty;
    float v = x[(size_t)b * C_ * N_ + (size_t)c * N_ + (n0 + tx)];
    v = (v - g_mean[c]) * g_rstd[c] * gamma[c] + beta[c];
    sh[ty][tx] = v;
    __syncthreads();
    g_t[((size_t)b * N_ + (n0 + ty)) * C_ + (c0 + tx)] = __float2half_rn(sh[tx][ty]);
}

// ---------------- launch ----------------
extern "C" void kernel_launch(void* const* d_in, const int* in_sizes, int n_in,
                              void* d_out, int out_size) {
    const float* x      = (const float*)d_in[0];
    const float* gamma  = (const float*)d_in[1];
    const float* beta   = (const float*)d_in[2];
    const float* W_kqv  = (const float*)d_in[3];
    const float* b_kqv  = (const float*)d_in[4];
    const float* W_proj = (const float*)d_in[5];
    const float* b_proj = (const float*)d_in[6];
    float* out = (float*)d_out;

    cudaFuncSetAttribute(tc_gemm<MODE_KQV >, cudaFuncAttributeMaxDynamicSharedMemorySize, SMEM_DYN);
    cudaFuncSetAttribute(tc_gemm<MODE_QK  >, cudaFuncAttributeMaxDynamicSharedMemorySize, SMEM_DYN);
    cudaFuncSetAttribute(tc_gemm<MODE_AV  >, cudaFuncAttributeMaxDynamicSharedMemorySize, SMEM_DYN);
    cudaFuncSetAttribute(tc_gemm<MODE_PROJ>, cudaFuncAttributeMaxDynamicSharedMemorySize, SMEM_DYN);

    void *pt, *pkqv, *ps, *pvt, *po, *pwk, *pwp;
    cudaGetSymbolAddress(&pt,   g_t);
    cudaGetSymbolAddress(&pkqv, g_kqv);
    cudaGetSymbolAddress(&ps,   g_s);
    cudaGetSymbolAddress(&pvt,  g_vt);
    cudaGetSymbolAddress(&po,   g_o);
    cudaGetSymbolAddress(&pwk,  g_wk);
    cudaGetSymbolAddress(&pwp,  g_wp);
    __half* t   = (__half*)pt;
    __half* kqv = (__half*)pkqv;
    __half* s   = (__half*)ps;
    __half* vt  = (__half*)pvt;
    __half* o   = (__half*)po;
    __half* wk  = (__half*)pwk;
    __half* wp  = (__half*)pwp;

    bn_stats_kernel<<<C_, 256>>>(x, W_kqv, W_proj);
    bn_apply_transpose_kernel<<<dim3(N_ / 32, C_ / 32, B_), dim3(32, 32)>>>(x, gamma, beta);

    // kqv: Q,K -> kqv; V tiles -> g_vt transposed
    tc_gemm<MODE_KQV><<<dim3(C3_ / 128, MTOT / 128, 1), NT, SMEM_DYN>>>(
        t, wk, b_kqv, kqv, nullptr, C_, C_, C_, C3_, 0L, 0L, 0L, 1.0f);

    // g_s = exp(q @ k^T / 16) per batch + expsum partials
    tc_gemm<MODE_QK><<<dim3(N_ / 128, N_ / 128, B_), NT, SMEM_DYN>>>(
        kqv, kqv + 256, nullptr, s, nullptr, C_, C3_, C3_, N_,
        (long)N_ * C3_, (long)N_ * C3_, (long)N_ * N_, 0.0625f);

    reduce_il_kernel<<<MTOT / 256, 256>>>();

    // o = (exp-scores @ v) * (1/l) : plain GEMM, scaling in epilogue
    tc_gemm<MODE_AV><<<dim3(C_ / 128, N_ / 128, B_), NT, SMEM_DYN>>>(
        s, vt, nullptr, o, nullptr, N_, N_, N_, C_,
        (long)N_ * N_, (long)C_ * N_, (long)N_ * C_, 1.0f);

    // fused proj: out[b,c,n] = (o @ W_proj^T + b_proj)^T + x
    tc_gemm<MODE_PROJ><<<dim3(C_ / 128, MTOT / 128, 1), NT, SMEM_DYN>>>(
        o, wp, b_proj, out, x, C_, C_, C_, 0, 0L, 0L, 0L, 1.0f);
}

// round 14
// speedup vs baseline: 1.2433x; 1.1384x over previous
#include <cuda_runtime.h>
#include <cuda_fp16.h>
#include <math.h>
#include <stdint.h>

// ---------------- problem constants ----------------
constexpr int B_   = 32;
constexpr int C_   = 256;
constexpr int N_   = 1024;
constexpr int C3_  = 768;
constexpr int MTOT = B_ * N_;   // 32768

// ---------------- scratch (half intermediates) ----------------
__device__ float  g_mean[C_];
__device__ float  g_rstd[C_];
__device__ __half g_t  [(size_t)MTOT * C_];    // [B,N,C]
__device__ __half g_kqv[(size_t)MTOT * C3_];   // [B,N,3C] (Q,K used)
__device__ __half g_s  [(size_t)B_ * N_ * N_]; // [B,N,N] exp(scores/16)
__device__ __half g_vt [(size_t)B_ * C_ * N_]; // [B,C,N] V^T
__device__ __half g_o  [(size_t)MTOT * C_];    // [B,N,C]
__device__ __half g_wk [(size_t)C3_ * C_];     // W_kqv fp16
__device__ __half g_wp [(size_t)C_ * C_];      // W_proj fp16
__device__ float  g_pl [(size_t)B_ * 8 * N_];  // per-tile row expsum
__device__ float  g_il [(size_t)B_ * N_];      // 1/rowsum

// ---------------- PTX helpers ----------------
__device__ __forceinline__ uint32_t smem_u32(const void* p) {
    return (uint32_t)__cvta_generic_to_shared(p);
}
__device__ __forceinline__ void mma_fp16(float c[4], const uint32_t a[4], const uint32_t b[2]) {
    asm volatile(
        "mma.sync.aligned.m16n8k16.row.col.f32.f16.f16.f32 "
        "{%0,%1,%2,%3}, {%4,%5,%6,%7}, {%8,%9}, {%0,%1,%2,%3};"
        : "+f"(c[0]), "+f"(c[1]), "+f"(c[2]), "+f"(c[3])
        : "r"(a[0]), "r"(a[1]), "r"(a[2]), "r"(a[3]), "r"(b[0]), "r"(b[1]));
}
#define LDSM_X4(r0, r1, r2, r3, addr) \
    asm volatile("ldmatrix.sync.aligned.m8n8.x4.shared.b16 {%0,%1,%2,%3}, [%4];" \
        : "=r"(r0), "=r"(r1), "=r"(r2), "=r"(r3) : "r"(addr))
#define CP_ASYNC16(dst, src) \
    asm volatile("cp.async.cg.shared.global [%0], [%1], 16;" :: "r"(dst), "l"(src))
#define CP_ASYNC_COMMIT() asm volatile("cp.async.commit_group;" ::: "memory")
#define CP_ASYNC_WAIT(n)  asm volatile("cp.async.wait_group %0;" :: "n"(n) : "memory")

// ---------------- fused fp16 GEMM family (fp32 accumulate) ----------------
// C = alpha * A * B^T; A [M,K] halves (lda), B [N,K] halves (ldb).
// CTA 128x128, K-chunk 64 halves, 256 thr = 2(M)x4(N) warps, warp 64x32.
// 3-stage cp.async pipe, prefetch distance 2, one barrier per chunk.
// All standard stores are smem-staged -> fully coalesced 16B STG.
constexpr int MODE_KQV  = 0;
constexpr int MODE_QK   = 1;
constexpr int MODE_AV   = 2;
constexpr int MODE_PROJ = 3;

constexpr int NT          = 256;
constexpr int ROW_B       = 144;                 // operand tile row stride (bytes)
constexpr int TILE_BYTES  = 128 * ROW_B;         // 18432
constexpr int STAGE_BYTES = 2 * TILE_BYTES;      // 36864
constexpr int SMEM_DYN    = 3 * STAGE_BYTES;     // 110592 (2 CTAs/SM)
constexpr int PS_ROW      = 136;                 // staging row stride (halves)

template <int MODE>
__global__ __launch_bounds__(NT, 2)
void tc_gemm(const __half* __restrict__ A, const __half* __restrict__ Bm,
             const float* __restrict__ bias, void* __restrict__ Cm,
             const void* __restrict__ P0,
             int K, int lda, int ldb, int ldc,
             long sA, long sB, long sC, float alpha) {
    extern __shared__ float sm[];

    const int tid  = threadIdx.x;
    const int lane = tid & 31;
    const int warp = tid >> 5;
    const int wm   = warp & 1;          // 0..1 (M)
    const int wn   = warp >> 1;         // 0..3 (N)
    const int g    = lane >> 2;
    const int q    = lane & 3;

    const int m0 = blockIdx.y * 128;
    const int n0 = blockIdx.x * 128;
    const __half* Ab = A  + (size_t)blockIdx.z * sA;
    const __half* Bb = Bm + (size_t)blockIdx.z * sB;

    const uint32_t smb = smem_u32(sm);

    const uint32_t a_lo =
        (uint32_t)((wm * 64 + (lane & 15)) * ROW_B + (lane >> 4) * 16);
    const uint32_t b_lo =
        (uint32_t)((wn * 32 + ((lane >> 4) & 1) * 8 + (lane & 7)) * ROW_B +
                   ((lane >> 3) & 1) * 16);

    auto load_stage = [&](int slot, int kc) {
        const uint32_t abase = smb + slot * STAGE_BYTES;
        const uint32_t bbase = abase + TILE_BYTES;
        const __half* Asrc = Ab + (size_t)m0 * lda + kc * 64;
        #pragma unroll
        for (int j = 0; j < 4; j++) {
            int i = tid + j * NT;
            int row = i >> 3, kg = i & 7;
            CP_ASYNC16(abase + (uint32_t)(row * ROW_B + kg * 16),
                       Asrc + (size_t)row * lda + kg * 8);
        }
        const __half* Bsrc = Bb + (size_t)n0 * ldb + kc * 64;
        #pragma unroll
        for (int j = 0; j < 4; j++) {
            int i = tid + j * NT;
            int row = i >> 3, kg = i & 7;
            CP_ASYNC16(bbase + (uint32_t)(row * ROW_B + kg * 16),
                       Bsrc + (size_t)row * ldb + kg * 8);
        }
        CP_ASYNC_COMMIT();
    };

    float acc[4][4][4] = {};
    const int nk = K >> 6;               // K-chunks of 64

    load_stage(0, 0);
    load_stage(1, 1);

    for (int ks = 0; ks < nk; ks++) {
        CP_ASYNC_WAIT(1);
        __syncthreads();
        if (ks + 2 < nk) load_stage((ks + 2) % 3, ks + 2);
        else             CP_ASYNC_COMMIT();

        const uint32_t abase = smb + (ks % 3) * STAGE_BYTES;
        const uint32_t bbase = abase + TILE_BYTES;

        #pragma unroll
        for (int kk = 0; kk < 4; kk++) {
            uint32_t af[4][4], bf[4][2];
            #pragma unroll
            for (int tm = 0; tm < 4; tm++) {
                LDSM_X4(af[tm][0], af[tm][1], af[tm][2], af[tm][3],
                        abase + a_lo + (uint32_t)(tm * 16 * ROW_B + kk * 32));
            }
            #pragma unroll
            for (int tnp = 0; tnp < 2; tnp++) {
                LDSM_X4(bf[2 * tnp][0], bf[2 * tnp][1], bf[2 * tnp + 1][0], bf[2 * tnp + 1][1],
                        bbase + b_lo + (uint32_t)(tnp * 16 * ROW_B + kk * 32));
            }
            #pragma unroll
            for (int tm = 0; tm < 4; tm++)
                #pragma unroll
                for (int tn = 0; tn < 4; tn++)
                    mma_fp16(acc[tm][tn], af[tm], bf[tn]);
        }
    }

    // ---------------- epilogues ----------------
    const bool transout = (MODE == MODE_PROJ) || (MODE == MODE_KQV && n0 >= 512);
    if (transout) {
        // acc^T via smem [c][r] (stride 68), then float4 LDS + vector I/O.
        __syncthreads();
        float* ws = sm + warp * (32 * 68);
        #pragma unroll
        for (int tm = 0; tm < 4; tm++) {
            #pragma unroll
            for (int tn = 0; tn < 4; tn++) {
                const int r  = tm * 16 + g;
                const int cb = tn * 8 + 2 * q;
                float b0 = __ldg(&bias[n0 + wn * 32 + cb]);
                float b1 = __ldg(&bias[n0 + wn * 32 + cb + 1]);
                ws[cb * 68 + r]           = acc[tm][tn][0] * alpha + b0;
                ws[(cb + 1) * 68 + r]     = acc[tm][tn][1] * alpha + b1;
                ws[cb * 68 + r + 8]       = acc[tm][tn][2] * alpha + b0;
                ws[(cb + 1) * 68 + r + 8] = acc[tm][tn][3] * alpha + b1;
            }
        }
        __syncwarp();
        const int b     = m0 >> 10;
        const int nbase = (m0 & 1023) + wm * 64;
        const int rq    = lane & 15;
        #pragma unroll
        for (int i = 0; i < 16; i++) {
            const int c = i * 2 + (lane >> 4);
            float4 v = *reinterpret_cast<float4*>(&ws[c * 68 + rq * 4]);
            if (MODE == MODE_PROJ) {
                const int cg = n0 + wn * 32 + c;
                const size_t o0 = (((size_t)(b * C_ + cg)) << 10) + nbase + rq * 4;
                float4 xv = __ldcs(reinterpret_cast<const float4*>((const float*)P0 + o0));
                v.x += xv.x; v.y += xv.y; v.z += xv.z; v.w += xv.w;
                __stcs(reinterpret_cast<float4*>((float*)Cm + o0), v);
            } else {
                const int cg = (n0 - 512) + wn * 32 + c;
                const size_t o0 = (((size_t)(b * C_ + cg)) << 10) + nbase + rq * 4;
                __half2 h0 = __floats2half2_rn(v.x, v.y);
                __half2 h1 = __floats2half2_rn(v.z, v.w);
                uint2 pk;
                pk.x = *reinterpret_cast<uint32_t*>(&h0);
                pk.y = *reinterpret_cast<uint32_t*>(&h1);
                *reinterpret_cast<uint2*>(&g_vt[o0]) = pk;
            }
        }
        return;
    }

    // standard epilogue: smem-staged, fully coalesced 16B stores
    {
        __half* Cb   = (__half*)Cm + (size_t)blockIdx.z * sC;
        __half* ps   = (__half*)sm;                 // staging: 128 x PS_ROW halves (34.8 KB)
        float*  redl = sm + 16384;                  // QK partials [4][128] @ +64KB
        __syncthreads();                            // operand buffers now free

        #pragma unroll
        for (int tm = 0; tm < 4; tm++) {
            const int r = wm * 64 + tm * 16 + g;
            float a0 = alpha, a1 = alpha;
            if (MODE == MODE_AV) {
                a0 = g_il[(size_t)blockIdx.z * N_ + m0 + r];
                a1 = g_il[(size_t)blockIdx.z * N_ + m0 + r + 8];
            }
            float s0 = 0.f, s1 = 0.f;
            #pragma unroll
            for (int tn = 0; tn < 4; tn++) {
                const int cl = wn * 32 + tn * 8 + 2 * q;
                float e0, e1, e2, e3;
                if (MODE == MODE_QK) {
                    e0 = __expf(acc[tm][tn][0] * alpha);
                    e1 = __expf(acc[tm][tn][1] * alpha);
                    e2 = __expf(acc[tm][tn][2] * alpha);
                    e3 = __expf(acc[tm][tn][3] * alpha);
                    s0 += e0 + e1;
                    s1 += e2 + e3;
                } else {
                    float b0 = 0.f, b1 = 0.f;
                    if (MODE == MODE_KQV) {
                        b0 = __ldg(&bias[n0 + cl]);
                        b1 = __ldg(&bias[n0 + cl + 1]);
                    }
                    e0 = acc[tm][tn][0] * a0 + b0;
                    e1 = acc[tm][tn][1] * a0 + b1;
                    e2 = acc[tm][tn][2] * a1 + b0;
                    e3 = acc[tm][tn][3] * a1 + b1;
                }
                __half2 v0 = __floats2half2_rn(e0, e1);
                __half2 v1 = __floats2half2_rn(e2, e3);
                *reinterpret_cast<__half2*>(&ps[r * PS_ROW + cl])       = v0;
                *reinterpret_cast<__half2*>(&ps[(r + 8) * PS_ROW + cl]) = v1;
            }
            if (MODE == MODE_QK) {
                s0 += __shfl_xor_sync(~0u, s0, 1);
                s0 += __shfl_xor_sync(~0u, s0, 2);
                s1 += __shfl_xor_sync(~0u, s1, 1);
                s1 += __shfl_xor_sync(~0u, s1, 2);
                if (q == 0) {
                    redl[wn * 128 + r]     = s0;
                    redl[wn * 128 + r + 8] = s1;
                }
            }
        }
        __syncthreads();

        // coalesced copy-out: 128 rows x 256 B
        #pragma unroll
        for (int it = 0; it < 8; it++) {
            const int idx = tid + it * 256;
            const int row = idx >> 4;
            const int seg = idx & 15;
            uint4 v = *reinterpret_cast<uint4*>(&ps[row * PS_ROW + seg * 8]);
            *reinterpret_cast<uint4*>(&Cb[(size_t)(m0 + row) * ldc + n0 + seg * 8]) = v;
        }

        if (MODE == MODE_QK) {
            if (tid < 128) {
                float l = redl[tid] + redl[128 + tid] + redl[256 + tid] + redl[384 + tid];
                g_pl[((size_t)blockIdx.z * 8 + blockIdx.x) * N_ + m0 + tid] = l;
            }
        }
    }
}

// ---------------- combine partials -> 1/rowsum -----------------
__global__ void reduce_il_kernel() {
    const int idx = blockIdx.x * 256 + threadIdx.x;
    const int b = idx >> 10, row = idx & 1023;
    float l = 0.f;
    #pragma unroll
    for (int t = 0; t < 8; t++)
        l += g_pl[((size_t)b * 8 + t) * N_ + row];
    g_il[(size_t)b * N_ + row] = 1.0f / l;
}

// ---------------- BN stats (float4) + fused weight conversion -------------
__global__ void bn_stats_kernel(const float* __restrict__ x,
                                const float* __restrict__ wk,
                                const float* __restrict__ wp) {
    const int c = blockIdx.x, tid = threadIdx.x;

    const int gidx = c * 256 + tid;                 // 0..65535
    #pragma unroll
    for (int i = gidx; i < C3_ * C_; i += 65536) g_wk[i] = __float2half_rn(wk[i]);
    g_wp[gidx] = __float2half_rn(wp[gidx]);

    float s = 0.f, ss = 0.f;
    const int NP4 = N_ / 4;
    for (int i = tid; i < B_ * NP4; i += 256) {
        int b = i >> 8, p4 = i & 255;
        float4 v = reinterpret_cast<const float4*>(
            x + (size_t)b * C_ * N_ + (size_t)c * N_)[p4];
        s  += v.x + v.y + v.z + v.w;
        ss += v.x * v.x + v.y * v.y + v.z * v.z + v.w * v.w;
    }
    __shared__ float sh1[256], sh2[256];
    sh1[tid] = s; sh2[tid] = ss;
    __syncthreads();
    for (int k = 128; k > 0; k >>= 1) {
        if (tid < k) { sh1[tid] += sh1[tid + k]; sh2[tid] += sh2[tid + k]; }
        __syncthreads();
    }
    if (tid == 0) {
        const float inv_n = 1.0f / (float)(B_ * N_);
        float mean = sh1[0] * inv_n;
        float var  = sh2[0] * inv_n - mean * mean;
        g_mean[c] = mean;
        g_rstd[c] = rsqrtf(var + 1e-5f);
    }
}

// ------- BN apply + transpose [B,C,N] -> [B,N,C] (fp16, vectorized) -------
__global__ __launch_bounds__(256)
void bn_apply_transpose_kernel(const float* __restrict__ x,
                               const float* __restrict__ gamma,
                               const float* __restrict__ beta) {
    __shared__ float sh[32][33];
    const int b = blockIdx.z, c0 = blockIdx.y * 32, n0 = blockIdx.x * 32;
    const int tid = threadIdx.x;
    {
        const int tx = tid & 7;        // n-quad
        const int ty = tid >> 3;       // c
        const int c  = c0 + ty;
        float4 v = *reinterpret_cast<const float4*>(
            &x[((size_t)b * C_ + c) * N_ + n0 + tx * 4]);
        const float rs = g_rstd[c] * gamma[c];
        const float be = beta[c] - g_mean[c] * rs;
        sh[ty][tx * 4 + 0] = v.x * rs + be;
        sh[ty][tx * 4 + 1] = v.y * rs + be;
        sh[ty][tx * 4 + 2] = v.z * rs + be;
        sh[ty][tx * 4 + 3] = v.w * rs + be;
    }
    __syncthreads();
    {
        const int n  = tid >> 3;       // 0..31
        const int cq = tid & 7;        // c-quad
        float f0 = sh[cq * 4 + 0][n];
        float f1 = sh[cq * 4 + 1][n];
        float f2 = sh[cq * 4 + 2][n];
        float f3 = sh[cq * 4 + 3][n];
        __half2 h0 = __floats2half2_rn(f0, f1);
        __half2 h1 = __floats2half2_rn(f2, f3);
        uint2 pk;
        pk.x = *reinterpret_cast<uint32_t*>(&h0);
        pk.y = *reinterpret_cast<uint32_t*>(&h1);
        *reinterpret_cast<uint2*>(
            &g_t[((size_t)b * N_ + n0 + n) * C_ + c0 + cq * 4]) = pk;
    }
}

// ---------------- launch ----------------
extern "C" void kernel_launch(void* const* d_in, const int* in_sizes, int n_in,
                              void* d_out, int out_size) {
    const float* x      = (const float*)d_in[0];
    const float* gamma  = (const float*)d_in[1];
    const float* beta   = (const float*)d_in[2];
    const float* W_kqv  = (const float*)d_in[3];
    const float* b_kqv  = (const float*)d_in[4];
    const float* W_proj = (const float*)d_in[5];
    const float* b_proj = (const float*)d_in[6];
    float* out = (float*)d_out;

    cudaFuncSetAttribute(tc_gemm<MODE_KQV >, cudaFuncAttributeMaxDynamicSharedMemorySize, SMEM_DYN);
    cudaFuncSetAttribute(tc_gemm<MODE_QK  >, cudaFuncAttributeMaxDynamicSharedMemorySize, SMEM_DYN);
    cudaFuncSetAttribute(tc_gemm<MODE_AV  >, cudaFuncAttributeMaxDynamicSharedMemorySize, SMEM_DYN);
    cudaFuncSetAttribute(tc_gemm<MODE_PROJ>, cudaFuncAttributeMaxDynamicSharedMemorySize, SMEM_DYN);

    void *pt, *pkqv, *ps, *pvt, *po, *pwk, *pwp;
    cudaGetSymbolAddress(&pt,   g_t);
    cudaGetSymbolAddress(&pkqv, g_kqv);
    cudaGetSymbolAddress(&ps,   g_s);
    cudaGetSymbolAddress(&pvt,  g_vt);
    cudaGetSymbolAddress(&po,   g_o);
    cudaGetSymbolAddress(&pwk,  g_wk);
    cudaGetSymbolAddress(&pwp,  g_wp);
    __half* t   = (__half*)pt;
    __half* kqv = (__half*)pkqv;
    __half* s   = (__half*)ps;
    __half* vt  = (__half*)pvt;
    __half* o   = (__half*)po;
    __half* wk  = (__half*)pwk;
    __half* wp  = (__half*)pwp;

    bn_stats_kernel<<<C_, 256>>>(x, W_kqv, W_proj);
    bn_apply_transpose_kernel<<<dim3(N_ / 32, C_ / 32, B_), 256>>>(x, gamma, beta);

    // kqv: Q,K -> kqv; V tiles -> g_vt transposed
    tc_gemm<MODE_KQV><<<dim3(C3_ / 128, MTOT / 128, 1), NT, SMEM_DYN>>>(
        t, wk, b_kqv, kqv, nullptr, C_, C_, C_, C3_, 0L, 0L, 0L, 1.0f);

    // g_s = exp(q @ k^T / 16) per batch + expsum partials
    tc_gemm<MODE_QK><<<dim3(N_ / 128, N_ / 128, B_), NT, SMEM_DYN>>>(
        kqv, kqv + 256, nullptr, s, nullptr, C_, C3_, C3_, N_,
        (long)N_ * C3_, (long)N_ * C3_, (long)N_ * N_, 0.0625f);

    reduce_il_kernel<<<MTOT / 256, 256>>>();

    // o = (exp-scores @ v) * (1/l) : plain GEMM, scaling in epilogue
    tc_gemm<MODE_AV><<<dim3(C_ / 128, N_ / 128, B_), NT, SMEM_DYN>>>(
        s, vt, nullptr, o, nullptr, N_, N_, N_, C_,
        (long)N_ * N_, (long)C_ * N_, (long)N_ * C_, 1.0f);

    // fused proj: out[b,c,n] = (o @ W_proj^T + b_proj)^T + x
    tc_gemm<MODE_PROJ><<<dim3(C_ / 128, MTOT / 128, 1), NT, SMEM_DYN>>>(
        o, wp, b_proj, out, x, C_, C_, C_, 0, 0L, 0L, 0L, 1.0f);
}

// round 15
// speedup vs baseline: 1.2541x; 1.0087x over previous
#include <cuda_runtime.h>
#include <cuda_fp16.h>
#include <math.h>
#include <stdint.h>

// ---------------- problem constants ----------------
constexpr int B_   = 32;
constexpr int C_   = 256;
constexpr int N_   = 1024;
constexpr int C3_  = 768;
constexpr int MTOT = B_ * N_;   // 32768

// ---------------- scratch (half intermediates) ----------------
__device__ float  g_mean[C_];
__device__ float  g_rstd[C_];
__device__ __half g_t  [(size_t)MTOT * C_];    // [B,N,C]
__device__ __half g_kqv[(size_t)MTOT * C3_];   // [B,N,3C]
__device__ __half g_s  [(size_t)B_ * N_ * N_]; // [B,N,N] exp(scores/16)
__device__ __half g_vp [(size_t)B_ * C_ * N_]; // [B,C,N]  Vp^T = Wp @ V^T
__device__ __half g_wk [(size_t)C3_ * C_];     // W_kqv fp16
__device__ __half g_wp [(size_t)C_ * C_];      // W_proj fp16
__device__ float  g_pl [(size_t)B_ * 8 * N_];  // per-tile row expsum
__device__ float  g_il [(size_t)B_ * N_];      // 1/rowsum

// ---------------- PTX helpers ----------------
__device__ __forceinline__ uint32_t smem_u32(const void* p) {
    return (uint32_t)__cvta_generic_to_shared(p);
}
__device__ __forceinline__ void mma_fp16(float c[4], const uint32_t a[4], const uint32_t b[2]) {
    asm volatile(
        "mma.sync.aligned.m16n8k16.row.col.f32.f16.f16.f32 "
        "{%0,%1,%2,%3}, {%4,%5,%6,%7}, {%8,%9}, {%0,%1,%2,%3};"
        : "+f"(c[0]), "+f"(c[1]), "+f"(c[2]), "+f"(c[3])
        : "r"(a[0]), "r"(a[1]), "r"(a[2]), "r"(a[3]), "r"(b[0]), "r"(b[1]));
}
#define LDSM_X4(r0, r1, r2, r3, addr) \
    asm volatile("ldmatrix.sync.aligned.m8n8.x4.shared.b16 {%0,%1,%2,%3}, [%4];" \
        : "=r"(r0), "=r"(r1), "=r"(r2), "=r"(r3) : "r"(addr))
#define CP_ASYNC16(dst, src) \
    asm volatile("cp.async.cg.shared.global [%0], [%1], 16;" :: "r"(dst), "l"(src))
#define CP_ASYNC_COMMIT() asm volatile("cp.async.commit_group;" ::: "memory")
#define CP_ASYNC_WAIT(n)  asm volatile("cp.async.wait_group %0;" :: "n"(n) : "memory")

// ---------------- fused fp16 GEMM family (fp32 accumulate) ----------------
// C = A * B^T; A [M,K] halves (lda), B [N,K] halves (ldb).
// CTA 128x128, K-chunk 64 halves, 256 thr = 2(M)x4(N) warps, warp 64x32.
// 3-stage cp.async pipe, prefetch distance 2, one barrier per chunk.
// Modes:
//  KQV : +bias; standard coalesced fp16 store (Q,K,V all into kqv).
//  QK  : stores exp(acc*alpha) fp16 + per-tile row expsum partials.
//  VPT : plain standard GEMM (Vp^T = Wp @ V^T).
//  AVP : out[b,co,n] = acc^T * (1/l_row) + b_proj[co] + x  (fused AV+proj).
constexpr int MODE_KQV = 0;
constexpr int MODE_QK  = 1;
constexpr int MODE_VPT = 2;
constexpr int MODE_AVP = 3;

constexpr int NT          = 256;
constexpr int ROW_B       = 144;                 // operand tile row stride (bytes)
constexpr int TILE_BYTES  = 128 * ROW_B;         // 18432
constexpr int STAGE_BYTES = 2 * TILE_BYTES;      // 36864
constexpr int SMEM_DYN    = 3 * STAGE_BYTES;     // 110592 (2 CTAs/SM)
constexpr int PS_ROW      = 136;                 // staging row stride (halves)

template <int MODE>
__global__ __launch_bounds__(NT, 2)
void tc_gemm(const __half* __restrict__ A, const __half* __restrict__ Bm,
             const float* __restrict__ bias, void* __restrict__ Cm,
             const void* __restrict__ P0,
             int K, int lda, int ldb, int ldc,
             long sA, long sB, long sC, float alpha) {
    extern __shared__ float sm[];

    const int tid  = threadIdx.x;
    const int lane = tid & 31;
    const int warp = tid >> 5;
    const int wm   = warp & 1;          // 0..1 (M)
    const int wn   = warp >> 1;         // 0..3 (N)
    const int g    = lane >> 2;
    const int q    = lane & 3;

    const int m0 = blockIdx.y * 128;
    const int n0 = blockIdx.x * 128;
    const __half* Ab = A  + (size_t)blockIdx.z * sA;
    const __half* Bb = Bm + (size_t)blockIdx.z * sB;

    const uint32_t smb = smem_u32(sm);

    const uint32_t a_lo =
        (uint32_t)((wm * 64 + (lane & 15)) * ROW_B + (lane >> 4) * 16);
    const uint32_t b_lo =
        (uint32_t)((wn * 32 + ((lane >> 4) & 1) * 8 + (lane & 7)) * ROW_B +
                   ((lane >> 3) & 1) * 16);

    auto load_stage = [&](int slot, int kc) {
        const uint32_t abase = smb + slot * STAGE_BYTES;
        const uint32_t bbase = abase + TILE_BYTES;
        const __half* Asrc = Ab + (size_t)m0 * lda + kc * 64;
        #pragma unroll
        for (int j = 0; j < 4; j++) {
            int i = tid + j * NT;
            int row = i >> 3, kg = i & 7;
            CP_ASYNC16(abase + (uint32_t)(row * ROW_B + kg * 16),
                       Asrc + (size_t)row * lda + kg * 8);
        }
        const __half* Bsrc = Bb + (size_t)n0 * ldb + kc * 64;
        #pragma unroll
        for (int j = 0; j < 4; j++) {
            int i = tid + j * NT;
            int row = i >> 3, kg = i & 7;
            CP_ASYNC16(bbase + (uint32_t)(row * ROW_B + kg * 16),
                       Bsrc + (size_t)row * ldb + kg * 8);
        }
        CP_ASYNC_COMMIT();
    };

    float acc[4][4][4] = {};
    const int nk = K >> 6;               // K-chunks of 64 (>=4 all call sites)

    load_stage(0, 0);
    load_stage(1, 1);

    for (int ks = 0; ks < nk; ks++) {
        CP_ASYNC_WAIT(1);
        __syncthreads();
        if (ks + 2 < nk) load_stage((ks + 2) % 3, ks + 2);
        else             CP_ASYNC_COMMIT();

        const uint32_t abase = smb + (ks % 3) * STAGE_BYTES;
        const uint32_t bbase = abase + TILE_BYTES;

        #pragma unroll
        for (int kk = 0; kk < 4; kk++) {
            uint32_t af[4][4], bf[4][2];
            #pragma unroll
            for (int tm = 0; tm < 4; tm++) {
                LDSM_X4(af[tm][0], af[tm][1], af[tm][2], af[tm][3],
                        abase + a_lo + (uint32_t)(tm * 16 * ROW_B + kk * 32));
            }
            #pragma unroll
            for (int tnp = 0; tnp < 2; tnp++) {
                LDSM_X4(bf[2 * tnp][0], bf[2 * tnp][1], bf[2 * tnp + 1][0], bf[2 * tnp + 1][1],
                        bbase + b_lo + (uint32_t)(tnp * 16 * ROW_B + kk * 32));
            }
            #pragma unroll
            for (int tm = 0; tm < 4; tm++)
                #pragma unroll
                for (int tn = 0; tn < 4; tn++)
                    mma_fp16(acc[tm][tn], af[tm], bf[tn]);
        }
    }

    // ---------------- epilogues ----------------
    if (MODE == MODE_AVP) {
        // out[b, co, n] = acc^T * (1/l_row) + b_proj[co] + x, coalesced on n.
        __syncthreads();
        float* ws = sm + warp * (32 * 68);
        const int bz = blockIdx.z;
        #pragma unroll
        for (int tm = 0; tm < 4; tm++) {
            const int r = tm * 16 + g;
            const float a0 = g_il[(size_t)bz * N_ + m0 + wm * 64 + r];
            const float a1 = g_il[(size_t)bz * N_ + m0 + wm * 64 + r + 8];
            #pragma unroll
            for (int tn = 0; tn < 4; tn++) {
                const int cb = tn * 8 + 2 * q;
                float b0 = __ldg(&bias[n0 + wn * 32 + cb]);
                float b1 = __ldg(&bias[n0 + wn * 32 + cb + 1]);
                ws[cb * 68 + r]           = acc[tm][tn][0] * a0 + b0;
                ws[(cb + 1) * 68 + r]     = acc[tm][tn][1] * a0 + b1;
                ws[cb * 68 + r + 8]       = acc[tm][tn][2] * a1 + b0;
                ws[(cb + 1) * 68 + r + 8] = acc[tm][tn][3] * a1 + b1;
            }
        }
        __syncwarp();
        const int nbase = m0 + wm * 64;
        const int rq    = lane & 15;
        #pragma unroll
        for (int i = 0; i < 16; i++) {
            const int c  = i * 2 + (lane >> 4);
            const int cg = n0 + wn * 32 + c;
            float4 v = *reinterpret_cast<float4*>(&ws[c * 68 + rq * 4]);
            const size_t o0 = (((size_t)(bz * C_ + cg)) << 10) + nbase + rq * 4;
            float4 xv = __ldcs(reinterpret_cast<const float4*>((const float*)P0 + o0));
            v.x += xv.x; v.y += xv.y; v.z += xv.z; v.w += xv.w;
            __stcs(reinterpret_cast<float4*>((float*)Cm + o0), v);
        }
        return;
    }

    // standard epilogue: smem-staged, fully coalesced 16B stores
    {
        __half* Cb   = (__half*)Cm + (size_t)blockIdx.z * sC;
        __half* ps   = (__half*)sm;                 // staging: 128 x PS_ROW halves
        float*  redl = sm + 16384;                  // QK partials [4][128] @ +64KB
        __syncthreads();

        #pragma unroll
        for (int tm = 0; tm < 4; tm++) {
            const int r = wm * 64 + tm * 16 + g;
            float s0 = 0.f, s1 = 0.f;
            #pragma unroll
            for (int tn = 0; tn < 4; tn++) {
                const int cl = wn * 32 + tn * 8 + 2 * q;
                float e0, e1, e2, e3;
                if (MODE == MODE_QK) {
                    e0 = __expf(acc[tm][tn][0] * alpha);
                    e1 = __expf(acc[tm][tn][1] * alpha);
                    e2 = __expf(acc[tm][tn][2] * alpha);
                    e3 = __expf(acc[tm][tn][3] * alpha);
                    s0 += e0 + e1;
                    s1 += e2 + e3;
                } else {
                    float b0 = 0.f, b1 = 0.f;
                    if (MODE == MODE_KQV) {
                        b0 = __ldg(&bias[n0 + cl]);
                        b1 = __ldg(&bias[n0 + cl + 1]);
                    }
                    e0 = acc[tm][tn][0] + b0;
                    e1 = acc[tm][tn][1] + b1;
                    e2 = acc[tm][tn][2] + b0;
                    e3 = acc[tm][tn][3] + b1;
                }
                __half2 v0 = __floats2half2_rn(e0, e1);
                __half2 v1 = __floats2half2_rn(e2, e3);
                *reinterpret_cast<__half2*>(&ps[r * PS_ROW + cl])       = v0;
                *reinterpret_cast<__half2*>(&ps[(r + 8) * PS_ROW + cl]) = v1;
            }
            if (MODE == MODE_QK) {
                s0 += __shfl_xor_sync(~0u, s0, 1);
                s0 += __shfl_xor_sync(~0u, s0, 2);
                s1 += __shfl_xor_sync(~0u, s1, 1);
                s1 += __shfl_xor_sync(~0u, s1, 2);
                if (q == 0) {
                    redl[wn * 128 + r]     = s0;
                    redl[wn * 128 + r + 8] = s1;
                }
            }
        }
        __syncthreads();

        // coalesced copy-out: 128 rows x 256 B
        #pragma unroll
        for (int it = 0; it < 8; it++) {
            const int idx = tid + it * 256;
            const int row = idx >> 4;
            const int seg = idx & 15;
            uint4 v = *reinterpret_cast<uint4*>(&ps[row * PS_ROW + seg * 8]);
            *reinterpret_cast<uint4*>(&Cb[(size_t)(m0 + row) * ldc + n0 + seg * 8]) = v;
        }

        if (MODE == MODE_QK) {
            if (tid < 128) {
                float l = redl[tid] + redl[128 + tid] + redl[256 + tid] + redl[384 + tid];
                g_pl[((size_t)blockIdx.z * 8 + blockIdx.x) * N_ + m0 + tid] = l;
            }
        }
    }
}

// ---------------- combine partials -> 1/rowsum -----------------
__global__ void reduce_il_kernel() {
    const int idx = blockIdx.x * 256 + threadIdx.x;
    const int b = idx >> 10, row = idx & 1023;
    float l = 0.f;
    #pragma unroll
    for (int t = 0; t < 8; t++)
        l += g_pl[((size_t)b * 8 + t) * N_ + row];
    g_il[(size_t)b * N_ + row] = 1.0f / l;
}

// ---------------- BN stats (float4) + fused weight conversion -------------
__global__ void bn_stats_kernel(const float* __restrict__ x,
                                const float* __restrict__ wk,
                                const float* __restrict__ wp) {
    const int c = blockIdx.x, tid = threadIdx.x;

    const int gidx = c * 256 + tid;                 // 0..65535
    #pragma unroll
    for (int i = gidx; i < C3_ * C_; i += 65536) g_wk[i] = __float2half_rn(wk[i]);
    g_wp[gidx] = __float2half_rn(wp[gidx]);

    float s = 0.f, ss = 0.f;
    const int NP4 = N_ / 4;
    for (int i = tid; i < B_ * NP4; i += 256) {
        int b = i >> 8, p4 = i & 255;
        float4 v = reinterpret_cast<const float4*>(
            x + (size_t)b * C_ * N_ + (size_t)c * N_)[p4];
        s  += v.x + v.y + v.z + v.w;
        ss += v.x * v.x + v.y * v.y + v.z * v.z + v.w * v.w;
    }
    __shared__ float sh1[256], sh2[256];
    sh1[tid] = s; sh2[tid] = ss;
    __syncthreads();
    for (int k = 128; k > 0; k >>= 1) {
        if (tid < k) { sh1[tid] += sh1[tid + k]; sh2[tid] += sh2[tid + k]; }
        __syncthreads();
    }
    if (tid == 0) {
        const float inv_n = 1.0f / (float)(B_ * N_);
        float mean = sh1[0] * inv_n;
        float var  = sh2[0] * inv_n - mean * mean;
        g_mean[c] = mean;
        g_rstd[c] = rsqrtf(var + 1e-5f);
    }
}

// ------- BN apply + transpose [B,C,N] -> [B,N,C] (fp16, vectorized) -------
__global__ __launch_bounds__(256)
void bn_apply_transpose_kernel(const float* __restrict__ x,
                               const float* __restrict__ gamma,
                               const float* __restrict__ beta) {
    __shared__ float sh[32][33];
    const int b = blockIdx.z, c0 = blockIdx.y * 32, n0 = blockIdx.x * 32;
    const int tid = threadIdx.x;
    {
        const int tx = tid & 7;        // n-quad
        const int ty = tid >> 3;       // c
        const int c  = c0 + ty;
        float4 v = *reinterpret_cast<const float4*>(
            &x[((size_t)b * C_ + c) * N_ + n0 + tx * 4]);
        const float rs = g_rstd[c] * gamma[c];
        const float be = beta[c] - g_mean[c] * rs;
        sh[ty][tx * 4 + 0] = v.x * rs + be;
        sh[ty][tx * 4 + 1] = v.y * rs + be;
        sh[ty][tx * 4 + 2] = v.z * rs + be;
        sh[ty][tx * 4 + 3] = v.w * rs + be;
    }
    __syncthreads();
    {
        const int n  = tid >> 3;       // 0..31
        const int cq = tid & 7;        // c-quad
        float f0 = sh[cq * 4 + 0][n];
        float f1 = sh[cq * 4 + 1][n];
        float f2 = sh[cq * 4 + 2][n];
        float f3 = sh[cq * 4 + 3][n];
        __half2 h0 = __floats2half2_rn(f0, f1);
        __half2 h1 = __floats2half2_rn(f2, f3);
        uint2 pk;
        pk.x = *reinterpret_cast<uint32_t*>(&h0);
        pk.y = *reinterpret_cast<uint32_t*>(&h1);
        *reinterpret_cast<uint2*>(
            &g_t[((size_t)b * N_ + n0 + n) * C_ + c0 + cq * 4]) = pk;
    }
}

// ---------------- launch ----------------
extern "C" void kernel_launch(void* const* d_in, const int* in_sizes, int n_in,
                              void* d_out, int out_size) {
    const float* x      = (const float*)d_in[0];
    const float* gamma  = (const float*)d_in[1];
    const float* beta   = (const float*)d_in[2];
    const float* W_kqv  = (const float*)d_in[3];
    const float* b_kqv  = (const float*)d_in[4];
    const float* W_proj = (const float*)d_in[5];
    const float* b_proj = (const float*)d_in[6];
    float* out = (float*)d_out;

    cudaFuncSetAttribute(tc_gemm<MODE_KQV>, cudaFuncAttributeMaxDynamicSharedMemorySize, SMEM_DYN);
    cudaFuncSetAttribute(tc_gemm<MODE_QK >, cudaFuncAttributeMaxDynamicSharedMemorySize, SMEM_DYN);
    cudaFuncSetAttribute(tc_gemm<MODE_VPT>, cudaFuncAttributeMaxDynamicSharedMemorySize, SMEM_DYN);
    cudaFuncSetAttribute(tc_gemm<MODE_AVP>, cudaFuncAttributeMaxDynamicSharedMemorySize, SMEM_DYN);

    void *pt, *pkqv, *ps, *pvp, *pwk, *pwp;
    cudaGetSymbolAddress(&pt,   g_t);
    cudaGetSymbolAddress(&pkqv, g_kqv);
    cudaGetSymbolAddress(&ps,   g_s);
    cudaGetSymbolAddress(&pvp,  g_vp);
    cudaGetSymbolAddress(&pwk,  g_wk);
    cudaGetSymbolAddress(&pwp,  g_wp);
    __half* t   = (__half*)pt;
    __half* kqv = (__half*)pkqv;
    __half* s   = (__half*)ps;
    __half* vp  = (__half*)pvp;
    __half* wk  = (__half*)pwk;
    __half* wp  = (__half*)pwp;

    bn_stats_kernel<<<C_, 256>>>(x, W_kqv, W_proj);
    bn_apply_transpose_kernel<<<dim3(N_ / 32, C_ / 32, B_), 256>>>(x, gamma, beta);

    // kqv = t @ W_kqv^T + b_kqv (standard coalesced store, Q|K|V)
    tc_gemm<MODE_KQV><<<dim3(C3_ / 128, MTOT / 128, 1), NT, SMEM_DYN>>>(
        t, wk, b_kqv, kqv, nullptr, C_, C_, C_, C3_, 0L, 0L, 0L, 1.0f);

    // g_s = exp(q @ k^T / 16) per batch + expsum partials
    tc_gemm<MODE_QK><<<dim3(N_ / 128, N_ / 128, B_), NT, SMEM_DYN>>>(
        kqv, kqv + 256, nullptr, s, nullptr, C_, C3_, C3_, N_,
        (long)N_ * C3_, (long)N_ * C3_, (long)N_ * N_, 0.0625f);

    reduce_il_kernel<<<MTOT / 256, 256>>>();

    // Vp^T[b, co, n] = Wp @ V^T : A = Wp [256,256], B = V rows of kqv
    tc_gemm<MODE_VPT><<<dim3(N_ / 128, C_ / 128, B_), NT, SMEM_DYN>>>(
        wp, kqv + 512, nullptr, vp, nullptr, C_, C_, C3_, N_,
        0L, (long)N_ * C3_, (long)C_ * N_, 1.0f);

    // out[b,co,n] = (exp-scores @ Vp^T)^T * (1/l) + b_proj + x
    tc_gemm<MODE_AVP><<<dim3(C_ / 128, N_ / 128, B_), NT, SMEM_DYN>>>(
        s, vp, b_proj, out, x, N_, N_, N_, 0,
        (long)N_ * N_, (long)C_ * N_, 0L, 1.0f);
}

// round 16
// speedup vs baseline: 1.3497x; 1.0762x over previous
#include <cuda_runtime.h>
#include <cuda_fp16.h>
#include <math.h>
#include <stdint.h>

// ---------------- problem constants ----------------
constexpr int B_   = 32;
constexpr int C_   = 256;
constexpr int N_   = 1024;
constexpr int C3_  = 768;
constexpr int MTOT = B_ * N_;   // 32768

// ---------------- scratch ----------------
__device__ float  g_mean[C_];
__device__ float  g_rstd[C_];
__device__ float2 g_ps [C_ * 16];              // per (channel, slice) partial sums
__device__ __half g_t  [(size_t)MTOT * C_];    // [B,N,C]
__device__ __half g_kqv[(size_t)MTOT * C3_];   // [B,N,3C]
__device__ __half g_s  [(size_t)B_ * N_ * N_]; // [B,N,N] exp(scores/16)
__device__ __half g_vp [(size_t)B_ * C_ * N_]; // [B,C,N]  Vp^T = Wp @ V^T
__device__ __half g_wk [(size_t)C3_ * C_];     // W_kqv fp16
__device__ __half g_wp [(size_t)C_ * C_];      // W_proj fp16
__device__ float  g_pl [(size_t)B_ * 8 * N_];  // per-tile row expsum

// ---------------- PTX helpers ----------------
__device__ __forceinline__ uint32_t smem_u32(const void* p) {
    return (uint32_t)__cvta_generic_to_shared(p);
}
__device__ __forceinline__ void mma_fp16(float c[4], const uint32_t a[4], const uint32_t b[2]) {
    asm volatile(
        "mma.sync.aligned.m16n8k16.row.col.f32.f16.f16.f32 "
        "{%0,%1,%2,%3}, {%4,%5,%6,%7}, {%8,%9}, {%0,%1,%2,%3};"
        : "+f"(c[0]), "+f"(c[1]), "+f"(c[2]), "+f"(c[3])
        : "r"(a[0]), "r"(a[1]), "r"(a[2]), "r"(a[3]), "r"(b[0]), "r"(b[1]));
}
#define LDSM_X4(r0, r1, r2, r3, addr) \
    asm volatile("ldmatrix.sync.aligned.m8n8.x4.shared.b16 {%0,%1,%2,%3}, [%4];" \
        : "=r"(r0), "=r"(r1), "=r"(r2), "=r"(r3) : "r"(addr))
#define CP_ASYNC16(dst, src) \
    asm volatile("cp.async.cg.shared.global [%0], [%1], 16;" :: "r"(dst), "l"(src))
#define CP_ASYNC_COMMIT() asm volatile("cp.async.commit_group;" ::: "memory")
#define CP_ASYNC_WAIT(n)  asm volatile("cp.async.wait_group %0;" :: "n"(n) : "memory")

// ---------------- shared GEMM geometry ----------------
constexpr int NT          = 256;
constexpr int ROW_B       = 144;                 // operand tile row stride (bytes)
constexpr int TILE_BYTES  = 128 * ROW_B;         // 18432
constexpr int STAGE_BYTES = 2 * TILE_BYTES;      // 36864
constexpr int SMEM_DYN    = 3 * STAGE_BYTES + 512; // 111104 (2 CTAs/SM)
constexpr int PS_ROW      = 136;                 // staging row stride (halves)
constexpr int IL_OFF      = 3 * STAGE_BYTES / 4; // float offset of il buffer (27648)

// mainloop macro body shared by all kernels (identical structure)
#define GEMM_MAINLOOP(Ab, lda, Bb, ldb, K)                                     \
    float acc[4][4][4] = {};                                                   \
    {                                                                          \
        const int nk = (K) >> 6;                                               \
        load_stage(0, 0);                                                      \
        load_stage(1, 1);                                                      \
        for (int ks = 0; ks < nk; ks++) {                                      \
            CP_ASYNC_WAIT(1);                                                  \
            __syncthreads();                                                   \
            if (ks + 2 < nk) load_stage((ks + 2) % 3, ks + 2);                 \
            else             CP_ASYNC_COMMIT();                                \
            const uint32_t abase = smb + (ks % 3) * STAGE_BYTES;               \
            const uint32_t bbase = abase + TILE_BYTES;                         \
            _Pragma("unroll")                                                  \
            for (int kk = 0; kk < 4; kk++) {                                   \
                uint32_t af[4][4], bf[4][2];                                   \
                _Pragma("unroll")                                              \
                for (int tm = 0; tm < 4; tm++) {                               \
                    LDSM_X4(af[tm][0], af[tm][1], af[tm][2], af[tm][3],        \
                            abase + a_lo + (uint32_t)(tm * 16 * ROW_B + kk * 32)); \
                }                                                              \
                _Pragma("unroll")                                              \
                for (int tnp = 0; tnp < 2; tnp++) {                            \
                    LDSM_X4(bf[2*tnp][0], bf[2*tnp][1], bf[2*tnp+1][0], bf[2*tnp+1][1], \
                            bbase + b_lo + (uint32_t)(tnp * 16 * ROW_B + kk * 32)); \
                }                                                              \
                _Pragma("unroll")                                              \
                for (int tm = 0; tm < 4; tm++)                                 \
                    _Pragma("unroll")                                          \
                    for (int tn = 0; tn < 4; tn++)                             \
                        mma_fp16(acc[tm][tn], af[tm], bf[tn]);                 \
            }                                                                  \
        }                                                                      \
    }

// ---------------- KQV GEMM: kqv = t @ wk^T + b_kqv ----------------
__global__ __launch_bounds__(NT, 2)
void kqv_kernel(const float* __restrict__ bias) {
    extern __shared__ float sm[];
    const int tid  = threadIdx.x;
    const int lane = tid & 31;
    const int warp = tid >> 5;
    const int wm   = warp & 1;
    const int wn   = warp >> 1;
    const int g    = lane >> 2;
    const int q    = lane & 3;
    const int m0   = blockIdx.y * 128;
    const int n0   = blockIdx.x * 128;
    const uint32_t smb = smem_u32(sm);

    const __half* Ab = g_t;
    const __half* Bb = g_wk;
    const int lda = C_, ldb = C_;

    const uint32_t a_lo =
        (uint32_t)((wm * 64 + (lane & 15)) * ROW_B + (lane >> 4) * 16);
    const uint32_t b_lo =
        (uint32_t)((wn * 32 + ((lane >> 4) & 1) * 8 + (lane & 7)) * ROW_B +
                   ((lane >> 3) & 1) * 16);

    auto load_stage = [&](int slot, int kc) {
        const uint32_t abase = smb + slot * STAGE_BYTES;
        const uint32_t bbase = abase + TILE_BYTES;
        const __half* Asrc = Ab + (size_t)m0 * lda + kc * 64;
        #pragma unroll
        for (int j = 0; j < 4; j++) {
            int i = tid + j * NT;
            int row = i >> 3, kg = i & 7;
            CP_ASYNC16(abase + (uint32_t)(row * ROW_B + kg * 16),
                       Asrc + (size_t)row * lda + kg * 8);
        }
        const __half* Bsrc = Bb + (size_t)n0 * ldb + kc * 64;
        #pragma unroll
        for (int j = 0; j < 4; j++) {
            int i = tid + j * NT;
            int row = i >> 3, kg = i & 7;
            CP_ASYNC16(bbase + (uint32_t)(row * ROW_B + kg * 16),
                       Bsrc + (size_t)row * ldb + kg * 8);
        }
        CP_ASYNC_COMMIT();
    };

    GEMM_MAINLOOP(Ab, lda, Bb, ldb, C_)

    // standard coalesced epilogue with bias
    __half* ps = (__half*)sm;
    __syncthreads();
    #pragma unroll
    for (int tm = 0; tm < 4; tm++) {
        const int r = wm * 64 + tm * 16 + g;
        #pragma unroll
        for (int tn = 0; tn < 4; tn++) {
            const int cl = wn * 32 + tn * 8 + 2 * q;
            float b0 = __ldg(&bias[n0 + cl]);
            float b1 = __ldg(&bias[n0 + cl + 1]);
            __half2 v0 = __floats2half2_rn(acc[tm][tn][0] + b0, acc[tm][tn][1] + b1);
            __half2 v1 = __floats2half2_rn(acc[tm][tn][2] + b0, acc[tm][tn][3] + b1);
            *reinterpret_cast<__half2*>(&ps[r * PS_ROW + cl])       = v0;
            *reinterpret_cast<__half2*>(&ps[(r + 8) * PS_ROW + cl]) = v1;
        }
    }
    __syncthreads();
    #pragma unroll
    for (int it = 0; it < 8; it++) {
        const int idx = tid + it * 256;
        const int row = idx >> 4;
        const int seg = idx & 15;
        uint4 v = *reinterpret_cast<uint4*>(&ps[row * PS_ROW + seg * 8]);
        *reinterpret_cast<uint4*>(&g_kqv[(size_t)(m0 + row) * C3_ + n0 + seg * 8]) = v;
    }
}

// ------- merged QK + VPT kernel: grid (10, 8, 32) --------------------------
// x < 8 : QK tile   (m0 = y*128 q-rows, n0 = x*128 keys)   -> g_s + partials
// x >= 8: VPT tile  (m0 = (x-8)*128 co,  n0 = y*128 keys)  -> g_vp
__global__ __launch_bounds__(NT, 2)
void qk_vpt_kernel() {
    extern __shared__ float sm[];
    const int tid  = threadIdx.x;
    const int lane = tid & 31;
    const int warp = tid >> 5;
    const int wm   = warp & 1;
    const int wn   = warp >> 1;
    const int g    = lane >> 2;
    const int q    = lane & 3;
    const int bz   = blockIdx.z;
    const bool isqk = (blockIdx.x < 8);
    const uint32_t smb = smem_u32(sm);

    int m0, n0, lda, ldb;
    const __half *Ab, *Bb;
    if (isqk) {
        m0 = blockIdx.y * 128;
        n0 = blockIdx.x * 128;
        Ab = g_kqv + (size_t)bz * N_ * C3_;           // q
        Bb = g_kqv + (size_t)bz * N_ * C3_ + 256;     // k
        lda = C3_; ldb = C3_;
    } else {
        m0 = (blockIdx.x - 8) * 128;                  // co tile
        n0 = blockIdx.y * 128;                        // key tile
        Ab = g_wp;
        Bb = g_kqv + (size_t)bz * N_ * C3_ + 512;     // v
        lda = C_; ldb = C3_;
    }

    const uint32_t a_lo =
        (uint32_t)((wm * 64 + (lane & 15)) * ROW_B + (lane >> 4) * 16);
    const uint32_t b_lo =
        (uint32_t)((wn * 32 + ((lane >> 4) & 1) * 8 + (lane & 7)) * ROW_B +
                   ((lane >> 3) & 1) * 16);

    auto load_stage = [&](int slot, int kc) {
        const uint32_t abase = smb + slot * STAGE_BYTES;
        const uint32_t bbase = abase + TILE_BYTES;
        const __half* Asrc = Ab + (size_t)m0 * lda + kc * 64;
        #pragma unroll
        for (int j = 0; j < 4; j++) {
            int i = tid + j * NT;
            int row = i >> 3, kg = i & 7;
            CP_ASYNC16(abase + (uint32_t)(row * ROW_B + kg * 16),
                       Asrc + (size_t)row * lda + kg * 8);
        }
        const __half* Bsrc = Bb + (size_t)n0 * ldb + kc * 64;
        #pragma unroll
        for (int j = 0; j < 4; j++) {
            int i = tid + j * NT;
            int row = i >> 3, kg = i & 7;
            CP_ASYNC16(bbase + (uint32_t)(row * ROW_B + kg * 16),
                       Bsrc + (size_t)row * ldb + kg * 8);
        }
        CP_ASYNC_COMMIT();
    };

    GEMM_MAINLOOP(Ab, lda, Bb, ldb, C_)

    __half* ps   = (__half*)sm;
    float*  redl = sm + 16384;
    __syncthreads();

    if (isqk) {
        const float alpha = 0.0625f;
        #pragma unroll
        for (int tm = 0; tm < 4; tm++) {
            const int r = wm * 64 + tm * 16 + g;
            float s0 = 0.f, s1 = 0.f;
            #pragma unroll
            for (int tn = 0; tn < 4; tn++) {
                const int cl = wn * 32 + tn * 8 + 2 * q;
                float e0 = __expf(acc[tm][tn][0] * alpha);
                float e1 = __expf(acc[tm][tn][1] * alpha);
                float e2 = __expf(acc[tm][tn][2] * alpha);
                float e3 = __expf(acc[tm][tn][3] * alpha);
                s0 += e0 + e1;
                s1 += e2 + e3;
                *reinterpret_cast<__half2*>(&ps[r * PS_ROW + cl])       = __floats2half2_rn(e0, e1);
                *reinterpret_cast<__half2*>(&ps[(r + 8) * PS_ROW + cl]) = __floats2half2_rn(e2, e3);
            }
            s0 += __shfl_xor_sync(~0u, s0, 1);
            s0 += __shfl_xor_sync(~0u, s0, 2);
            s1 += __shfl_xor_sync(~0u, s1, 1);
            s1 += __shfl_xor_sync(~0u, s1, 2);
            if (q == 0) {
                redl[wn * 128 + r]     = s0;
                redl[wn * 128 + r + 8] = s1;
            }
        }
    } else {
        #pragma unroll
        for (int tm = 0; tm < 4; tm++) {
            const int r = wm * 64 + tm * 16 + g;
            #pragma unroll
            for (int tn = 0; tn < 4; tn++) {
                const int cl = wn * 32 + tn * 8 + 2 * q;
                *reinterpret_cast<__half2*>(&ps[r * PS_ROW + cl]) =
                    __floats2half2_rn(acc[tm][tn][0], acc[tm][tn][1]);
                *reinterpret_cast<__half2*>(&ps[(r + 8) * PS_ROW + cl]) =
                    __floats2half2_rn(acc[tm][tn][2], acc[tm][tn][3]);
            }
        }
    }
    __syncthreads();

    __half* Cb = isqk ? (g_s  + (size_t)bz * N_ * N_)
                      : (g_vp + (size_t)bz * C_ * N_);
    const int ldc = N_;
    #pragma unroll
    for (int it = 0; it < 8; it++) {
        const int idx = tid + it * 256;
        const int row = idx >> 4;
        const int seg = idx & 15;
        uint4 v = *reinterpret_cast<uint4*>(&ps[row * PS_ROW + seg * 8]);
        *reinterpret_cast<uint4*>(&Cb[(size_t)(m0 + row) * ldc + n0 + seg * 8]) = v;
    }

    if (isqk && tid < 128) {
        float l = redl[tid] + redl[128 + tid] + redl[256 + tid] + redl[384 + tid];
        g_pl[((size_t)bz * 8 + blockIdx.x) * N_ + m0 + tid] = l;
    }
}

// ------- AVP kernel: out[b,co,n] = (expS @ Vp^T)^T / l + b_proj + x --------
__global__ __launch_bounds__(NT, 2)
void avp_kernel(const float* __restrict__ bias, float* __restrict__ Cm,
                const float* __restrict__ xr) {
    extern __shared__ float sm[];
    const int tid  = threadIdx.x;
    const int lane = tid & 31;
    const int warp = tid >> 5;
    const int wm   = warp & 1;
    const int wn   = warp >> 1;
    const int g    = lane >> 2;
    const int q    = lane & 3;
    const int bz   = blockIdx.z;
    const int m0   = blockIdx.y * 128;   // q rows
    const int n0   = blockIdx.x * 128;   // co
    const uint32_t smb = smem_u32(sm);

    // fold reduce_il: per-row 1/sum into dedicated smem (beyond stage area)
    float* sm_il = sm + IL_OFF;
    if (tid < 128) {
        float l = 0.f;
        #pragma unroll
        for (int t = 0; t < 8; t++)
            l += g_pl[((size_t)bz * 8 + t) * N_ + m0 + tid];
        sm_il[tid] = 1.0f / l;
    }

    const __half* Ab = g_s  + (size_t)bz * N_ * N_;
    const __half* Bb = g_vp + (size_t)bz * C_ * N_;
    const int lda = N_, ldb = N_;

    const uint32_t a_lo =
        (uint32_t)((wm * 64 + (lane & 15)) * ROW_B + (lane >> 4) * 16);
    const uint32_t b_lo =
        (uint32_t)((wn * 32 + ((lane >> 4) & 1) * 8 + (lane & 7)) * ROW_B +
                   ((lane >> 3) & 1) * 16);

    auto load_stage = [&](int slot, int kc) {
        const uint32_t abase = smb + slot * STAGE_BYTES;
        const uint32_t bbase = abase + TILE_BYTES;
        const __half* Asrc = Ab + (size_t)m0 * lda + kc * 64;
        #pragma unroll
        for (int j = 0; j < 4; j++) {
            int i = tid + j * NT;
            int row = i >> 3, kg = i & 7;
            CP_ASYNC16(abase + (uint32_t)(row * ROW_B + kg * 16),
                       Asrc + (size_t)row * lda + kg * 8);
        }
        const __half* Bsrc = Bb + (size_t)n0 * ldb + kc * 64;
        #pragma unroll
        for (int j = 0; j < 4; j++) {
            int i = tid + j * NT;
            int row = i >> 3, kg = i & 7;
            CP_ASYNC16(bbase + (uint32_t)(row * ROW_B + kg * 16),
                       Bsrc + (size_t)row * ldb + kg * 8);
        }
        CP_ASYNC_COMMIT();
    };

    GEMM_MAINLOOP(Ab, lda, Bb, ldb, N_)

    // transposed epilogue with 1/l scaling + bias + residual
    __syncthreads();
    float* ws = sm + warp * (32 * 68);
    #pragma unroll
    for (int tm = 0; tm < 4; tm++) {
        const int r = tm * 16 + g;
        const float a0 = sm_il[wm * 64 + r];
        const float a1 = sm_il[wm * 64 + r + 8];
        #pragma unroll
        for (int tn = 0; tn < 4; tn++) {
            const int cb = tn * 8 + 2 * q;
            float b0 = __ldg(&bias[n0 + wn * 32 + cb]);
            float b1 = __ldg(&bias[n0 + wn * 32 + cb + 1]);
            ws[cb * 68 + r]           = acc[tm][tn][0] * a0 + b0;
            ws[(cb + 1) * 68 + r]     = acc[tm][tn][1] * a0 + b1;
            ws[cb * 68 + r + 8]       = acc[tm][tn][2] * a1 + b0;
            ws[(cb + 1) * 68 + r + 8] = acc[tm][tn][3] * a1 + b1;
        }
    }
    __syncwarp();
    const int nbase = m0 + wm * 64;
    const int rq    = lane & 15;
    #pragma unroll
    for (int i = 0; i < 16; i++) {
        const int c  = i * 2 + (lane >> 4);
        const int cg = n0 + wn * 32 + c;
        float4 v = *reinterpret_cast<float4*>(&ws[c * 68 + rq * 4]);
        const size_t o0 = (((size_t)(bz * C_ + cg)) << 10) + nbase + rq * 4;
        float4 xv = __ldcs(reinterpret_cast<const float4*>(xr + o0));
        v.x += xv.x; v.y += xv.y; v.z += xv.z; v.w += xv.w;
        __stcs(reinterpret_cast<float4*>(Cm + o0), v);
    }
}

// ---------------- BN stats stage A: partial sums (grid 16 x 256) ----------
__global__ void bn_partial_kernel(const float* __restrict__ x,
                                  const float* __restrict__ wk,
                                  const float* __restrict__ wp) {
    const int sl = blockIdx.x;      // 0..15 (pair of batches)
    const int c  = blockIdx.y;      // channel
    const int tid = threadIdx.x;

    if (sl == 0) {                  // fused weight conversion on slice-0 blocks
        const int gidx = c * 256 + tid;
        #pragma unroll
        for (int i = gidx; i < C3_ * C_; i += 65536) g_wk[i] = __float2half_rn(wk[i]);
        g_wp[gidx] = __float2half_rn(wp[gidx]);
    }

    float s = 0.f, ss = 0.f;
    #pragma unroll
    for (int j = 0; j < 2; j++) {
        const int b = sl * 2 + j;
        float4 v = reinterpret_cast<const float4*>(
            x + ((size_t)b * C_ + c) * N_)[tid];
        s  += v.x + v.y + v.z + v.w;
        ss += v.x * v.x + v.y * v.y + v.z * v.z + v.w * v.w;
    }
    __shared__ float sh1[256], sh2[256];
    sh1[tid] = s; sh2[tid] = ss;
    __syncthreads();
    for (int k = 128; k > 0; k >>= 1) {
        if (tid < k) { sh1[tid] += sh1[tid + k]; sh2[tid] += sh2[tid + k]; }
        __syncthreads();
    }
    if (tid == 0) g_ps[c * 16 + sl] = make_float2(sh1[0], sh2[0]);
}

// ---------------- BN stats stage B: combine (grid 1, 256 thr) -------------
__global__ void bn_combine_kernel() {
    const int c = threadIdx.x;
    float s = 0.f, ss = 0.f;
    #pragma unroll
    for (int t = 0; t < 16; t++) {
        float2 p = g_ps[c * 16 + t];
        s += p.x; ss += p.y;
    }
    const float inv_n = 1.0f / (float)(B_ * N_);
    float mean = s * inv_n;
    float var  = ss * inv_n - mean * mean;
    g_mean[c] = mean;
    g_rstd[c] = rsqrtf(var + 1e-5f);
}

// ------- BN apply + transpose [B,C,N] -> [B,N,C] (fp16, vectorized) -------
__global__ __launch_bounds__(256)
void bn_apply_transpose_kernel(const float* __restrict__ x,
                               const float* __restrict__ gamma,
                               const float* __restrict__ beta) {
    __shared__ float sh[32][33];
    const int b = blockIdx.z, c0 = blockIdx.y * 32, n0 = blockIdx.x * 32;
    const int tid = threadIdx.x;
    {
        const int tx = tid & 7;
        const int ty = tid >> 3;
        const int c  = c0 + ty;
        float4 v = *reinterpret_cast<const float4*>(
            &x[((size_t)b * C_ + c) * N_ + n0 + tx * 4]);
        const float rs = g_rstd[c] * gamma[c];
        const float be = beta[c] - g_mean[c] * rs;
        sh[ty][tx * 4 + 0] = v.x * rs + be;
        sh[ty][tx * 4 + 1] = v.y * rs + be;
        sh[ty][tx * 4 + 2] = v.z * rs + be;
        sh[ty][tx * 4 + 3] = v.w * rs + be;
    }
    __syncthreads();
    {
        const int n  = tid >> 3;
        const int cq = tid & 7;
        __half2 h0 = __floats2half2_rn(sh[cq * 4 + 0][n], sh[cq * 4 + 1][n]);
        __half2 h1 = __floats2half2_rn(sh[cq * 4 + 2][n], sh[cq * 4 + 3][n]);
        uint2 pk;
        pk.x = *reinterpret_cast<uint32_t*>(&h0);
        pk.y = *reinterpret_cast<uint32_t*>(&h1);
        *reinterpret_cast<uint2*>(
            &g_t[((size_t)b * N_ + n0 + n) * C_ + c0 + cq * 4]) = pk;
    }
}

// ---------------- launch ----------------
extern "C" void kernel_launch(void* const* d_in, const int* in_sizes, int n_in,
                              void* d_out, int out_size) {
    const float* x      = (const float*)d_in[0];
    const float* gamma  = (const float*)d_in[1];
    const float* beta   = (const float*)d_in[2];
    const float* W_kqv  = (const float*)d_in[3];
    const float* b_kqv  = (const float*)d_in[4];
    const float* W_proj = (const float*)d_in[5];
    const float* b_proj = (const float*)d_in[6];
    float* out = (float*)d_out;

    cudaFuncSetAttribute(kqv_kernel,    cudaFuncAttributeMaxDynamicSharedMemorySize, SMEM_DYN);
    cudaFuncSetAttribute(qk_vpt_kernel, cudaFuncAttributeMaxDynamicSharedMemorySize, SMEM_DYN);
    cudaFuncSetAttribute(avp_kernel,    cudaFuncAttributeMaxDynamicSharedMemorySize, SMEM_DYN);

    // BN stats (parallel) + weight conversion
    bn_partial_kernel<<<dim3(16, C_), 256>>>(x, W_kqv, W_proj);
    bn_combine_kernel<<<1, C_>>>();
    bn_apply_transpose_kernel<<<dim3(N_ / 32, C_ / 32, B_), 256>>>(x, gamma, beta);

    // kqv = t @ W_kqv^T + b_kqv
    kqv_kernel<<<dim3(C3_ / 128, MTOT / 128, 1), NT, SMEM_DYN>>>(b_kqv);

    // merged: g_s = exp(q k^T/16) + partials  ||  g_vp = Wp @ V^T
    qk_vpt_kernel<<<dim3(10, 8, B_), NT, SMEM_DYN>>>();

    // out = (expS @ Vp^T)^T / l + b_proj + x   (reduce folded into prologue)
    avp_kernel<<<dim3(C_ / 128, N_ / 128, B_), NT, SMEM_DYN>>>(b_proj, out, x);
}